// round 11
// baseline (speedup 1.0000x reference)
#include <cuda_runtime.h>
#include <math.h>
#include <stdint.h>

#define D 512
#define NMAX 20000
#define EMAX 320000

// k-permutation for GEMM INPUT tensors (g_t, g_Wc, g_attn): within each
// 8-k group, k=j stored at position 2*(j&3) + (j>>2)  (order 0,4,1,5,2,6,3,7)
// -> thread fragment pair (tg, tg+4) is contiguous -> LDS.64 in the GEMM.
__device__ __forceinline__ int kperm(int j) { return 2 * (j & 3) + (j >> 2); }

// ---------------- scratch (device globals: allocation-free) ----------------
__device__ float g_t[NMAX * D];      // tangent vectors, tf32-rounded, k-permuted
__device__ float g_q[NMAX * D];      // q ; later reused as h (normal layout)
__device__ float g_k[NMAX * D];
__device__ float g_v[NMAX * D];
__device__ float g_attn[NMAX * D];   // tf32-rounded, k-permuted
__device__ float g_Wc[4 * D * D];    // tf32-rounded weights, k-permuted
__device__ float g_scores[EMAX];
__device__ float g_inv[NMAX];
__device__ int   g_cnt[NMAX];
__device__ int   g_off[NMAX + 1];
__device__ int   g_cur[NMAX];
__device__ int   g_srcs[EMAX];

__device__ __forceinline__ float f2tf32(float x) {
    uint32_t u;
    asm("cvt.rna.tf32.f32 %0, %1;" : "=r"(u) : "f"(x));
    return __uint_as_float(u);
}

__device__ __forceinline__ void cp_async16(void* sptr, const void* gptr, bool pred) {
    uint32_t sa = (uint32_t)__cvta_generic_to_shared(sptr);
    int sz = pred ? 16 : 0;
    asm volatile("cp.async.cg.shared.global [%0], [%1], 16, %2;\n"
                 :: "r"(sa), "l"(gptr), "r"(sz));
}

// ---------------- W conversion (tf32 round + k-permute) --------------------
__global__ void convw_kernel(const float* __restrict__ Wq, const float* __restrict__ Wk,
                             const float* __restrict__ Wv, const float* __restrict__ Wo) {
    int i = blockIdx.x * blockDim.x + threadIdx.x;   // float4 index
    int total = 4 * D * D / 4;
    if (i >= total) return;
    int which = i / (D * D / 4);
    int off = i - which * (D * D / 4);
    const float* src = (which == 0) ? Wq : (which == 1) ? Wk : (which == 2) ? Wv : Wo;
    float4 v = ((const float4*)src)[off];
    float vs[4] = {f2tf32(v.x), f2tf32(v.y), f2tf32(v.z), f2tf32(v.w)};
    int base = off * 4;                  // flat element index within matrix
    int row = base >> 9;                 // /512
    int k0 = base & 511;
    float* drow = g_Wc + (size_t)which * D * D + (size_t)row * D;
#pragma unroll
    for (int c = 0; c < 4; c++) {
        int k = k0 + c;
        drow[(k & ~7) + kperm(k & 7)] = vs[c];
    }
}

// ---------------- logmap0 (tf32-rounded, k-permuted output) ----------------
__global__ void logmap_kernel(const float* __restrict__ x, int n) {
    int row = blockIdx.x;
    if (row >= n) return;
    const float4* xr = (const float4*)(x + (size_t)row * D);
    float4 xv = xr[threadIdx.x];
    float ss = xv.x * xv.x + xv.y * xv.y + xv.z * xv.z + xv.w * xv.w;
    for (int o = 16; o > 0; o >>= 1) ss += __shfl_down_sync(0xffffffffu, ss, o);
    __shared__ float sred[4];
    int lane = threadIdx.x & 31, w = threadIdx.x >> 5;
    if (lane == 0) sred[w] = ss;
    __syncthreads();
    float tot = sred[0] + sred[1] + sred[2] + sred[3];
    float nrm = sqrtf(tot);
    float nc = fminf(fmaxf(nrm, 1e-7f), 1.f - 1e-6f);
    float fac = atanhf(nc) / nc;
    float vs[4] = {f2tf32(fac * xv.x), f2tf32(fac * xv.y),
                   f2tf32(fac * xv.z), f2tf32(fac * xv.w)};
    float* drow = g_t + (size_t)row * D;
    int k0 = threadIdx.x * 4;
#pragma unroll
    for (int c = 0; c < 4; c++) {
        int k = k0 + c;
        drow[(k & ~7) + kperm(k & 7)] = vs[c];
    }
}

// ---------------- expmap0 (reads g_q as h, normal layout) ------------------
__global__ void expmap_kernel(float* __restrict__ out, int n) {
    int row = blockIdx.x;
    if (row >= n) return;
    const float4* hr = (const float4*)(g_q + (size_t)row * D);
    float4 hv = hr[threadIdx.x];
    float ss = hv.x * hv.x + hv.y * hv.y + hv.z * hv.z + hv.w * hv.w;
    for (int o = 16; o > 0; o >>= 1) ss += __shfl_down_sync(0xffffffffu, ss, o);
    __shared__ float sred[4];
    int lane = threadIdx.x & 31, w = threadIdx.x >> 5;
    if (lane == 0) sred[w] = ss;
    __syncthreads();
    float tot = sred[0] + sred[1] + sred[2] + sred[3];
    float nrm = sqrtf(tot);
    float nc = fmaxf(nrm, 1e-7f);
    float fac = tanhf(nc) / nc;
    float4 o4;
    o4.x = fac * hv.x; o4.y = fac * hv.y; o4.z = fac * hv.z; o4.w = fac * hv.w;
    ((float4*)(out + (size_t)row * D))[threadIdx.x] = o4;
}

// ---------------- TF32 tensor-core GEMM (3-stage, LDS.64 fragments) --------
//   C[M,512] = (A[M,512] @ W[512,512]^T + bias) * scale
// A and W are k-permuted; fragment pairs (tg, tg+4) load as one float2.
#define SM_STRIDE 36
#define TILE_FLOATS (128 * SM_STRIDE)
#define NSTAGE 3
#define GEMM_SMEM (NSTAGE * 2 * TILE_FLOATS * 4)

__global__ __launch_bounds__(256, 2)
void tgemm_kernel(const float* __restrict__ b0, const float* __restrict__ b1,
                  const float* __restrict__ b2, int sel_base, int M, float qscale) {
    extern __shared__ float smem[];
    int sel = sel_base + (blockIdx.x >> 2);
    int bn = (blockIdx.x & 3) << 7;
    const float* __restrict__ A = (sel == 3) ? g_attn : g_t;
    const float* __restrict__ W = g_Wc + (size_t)sel * D * D;
    float* __restrict__ C = (sel == 1) ? g_k : (sel == 2) ? g_v : g_q;
    const float* __restrict__ bias = (sel == 1) ? b1 : (sel == 2) ? b2 : b0;
    float scale = (sel == 0) ? qscale : 1.f;

    int bm = blockIdx.y * 128;
    int tid = threadIdx.x;
    int lane = tid & 31, warp = tid >> 5;
    int wm = (warp >> 2) * 64;
    int wn = (warp & 3) * 32;
    int g = lane >> 2, tg = lane & 3;
    int lrow = tid >> 3, lcol = (tid & 7) << 2;

    float acc[4][4][4];
#pragma unroll
    for (int mt = 0; mt < 4; mt++)
#pragma unroll
        for (int nt = 0; nt < 4; nt++)
#pragma unroll
            for (int i = 0; i < 4; i++) acc[mt][nt][i] = 0.f;

    auto prefetch = [&](int it) {
        float* As = smem + (it % NSTAGE) * 2 * TILE_FLOATS;
        float* Ws = As + TILE_FLOATS;
        int k0 = it * 32;
#pragma unroll
        for (int i = 0; i < 4; i++) {
            int row = lrow + i * 32;
            int ga = bm + row;
            cp_async16(&As[row * SM_STRIDE + lcol],
                       A + (size_t)ga * D + k0 + lcol, ga < M);
            cp_async16(&Ws[row * SM_STRIDE + lcol],
                       W + (size_t)(bn + row) * D + k0 + lcol, true);
        }
        asm volatile("cp.async.commit_group;\n" ::);
    };

    prefetch(0);
    prefetch(1);

    for (int it = 0; it < 16; it++) {
        if (it < 15) {
            asm volatile("cp.async.wait_group 1;\n" ::);
        } else {
            asm volatile("cp.async.wait_group 0;\n" ::);
        }
        __syncthreads();
        if (it + 2 < 16) prefetch(it + 2);

        const float* As = smem + (it % NSTAGE) * 2 * TILE_FLOATS;
        const float* Ws = As + TILE_FLOATS;

#pragma unroll
        for (int ks = 0; ks < 4; ks++) {
            int kb = ks * 8;           // physical group base (perm is in-group)
            int kc = kb + 2 * tg;      // this thread's contiguous pair
            uint32_t af[4][4], bf[4][2];
#pragma unroll
            for (int mt = 0; mt < 4; mt++) {
                int r = wm + mt * 16 + g;
                float2 alo = *(const float2*)&As[r * SM_STRIDE + kc];
                float2 ahi = *(const float2*)&As[(r + 8) * SM_STRIDE + kc];
                af[mt][0] = __float_as_uint(alo.x);   // (r,   tg)
                af[mt][1] = __float_as_uint(ahi.x);   // (r+8, tg)
                af[mt][2] = __float_as_uint(alo.y);   // (r,   tg+4)
                af[mt][3] = __float_as_uint(ahi.y);   // (r+8, tg+4)
            }
#pragma unroll
            for (int nt = 0; nt < 4; nt++) {
                int r = wn + nt * 8 + g;
                float2 bv = *(const float2*)&Ws[r * SM_STRIDE + kc];
                bf[nt][0] = __float_as_uint(bv.x);
                bf[nt][1] = __float_as_uint(bv.y);
            }
#pragma unroll
            for (int mt = 0; mt < 4; mt++)
#pragma unroll
                for (int nt = 0; nt < 4; nt++) {
                    asm volatile(
                        "mma.sync.aligned.m16n8k8.row.col.f32.tf32.tf32.f32 "
                        "{%0,%1,%2,%3}, {%4,%5,%6,%7}, {%8,%9}, {%0,%1,%2,%3};"
                        : "+f"(acc[mt][nt][0]), "+f"(acc[mt][nt][1]),
                          "+f"(acc[mt][nt][2]), "+f"(acc[mt][nt][3])
                        : "r"(af[mt][0]), "r"(af[mt][1]),
                          "r"(af[mt][2]), "r"(af[mt][3]),
                          "r"(bf[nt][0]), "r"(bf[nt][1]));
                }
        }
    }

#pragma unroll
    for (int mt = 0; mt < 4; mt++) {
        int row0 = bm + wm + mt * 16 + g;
#pragma unroll
        for (int nt = 0; nt < 4; nt++) {
            int col = bn + wn + nt * 8 + tg * 2;
            float b0v = bias[col], b1v = bias[col + 1];
            if (row0 < M) {
                float2 o;
                o.x = (acc[mt][nt][0] + b0v) * scale;
                o.y = (acc[mt][nt][1] + b1v) * scale;
                *(float2*)(C + (size_t)row0 * D + col) = o;
            }
            if (row0 + 8 < M) {
                float2 o;
                o.x = (acc[mt][nt][2] + b0v) * scale;
                o.y = (acc[mt][nt][3] + b1v) * scale;
                *(float2*)(C + (size_t)(row0 + 8) * D + col) = o;
            }
        }
    }
}

// ---------------- CSR build (by dst) ----------------
__global__ void zero_cnt_kernel(int n) {
    int i = blockIdx.x * blockDim.x + threadIdx.x;
    if (i < n) g_cnt[i] = 0;
}
__global__ void hist_kernel(const int* __restrict__ dst, int E) {
    int i = blockIdx.x * blockDim.x + threadIdx.x;
    if (i < E) atomicAdd(&g_cnt[dst[i]], 1);
}
__global__ void scan_kernel(int n) {
    __shared__ int sdata[1024];
    __shared__ int carry_s;
    int t = threadIdx.x;
    if (t == 0) carry_s = 0;
    __syncthreads();
    for (int base = 0; base < n; base += 1024) {
        int idx = base + t;
        int v = (idx < n) ? g_cnt[idx] : 0;
        sdata[t] = v;
        __syncthreads();
        for (int off = 1; off < 1024; off <<= 1) {
            int tmp = (t >= off) ? sdata[t - off] : 0;
            __syncthreads();
            sdata[t] += tmp;
            __syncthreads();
        }
        int incl = sdata[t];
        int carry = carry_s;
        if (idx < n) {
            int excl = carry + incl - v;
            g_off[idx] = excl;
            g_cur[idx] = excl;
        }
        __syncthreads();
        if (t == 1023) carry_s = carry + incl;
        __syncthreads();
    }
    if (t == 0) g_off[n] = carry_s;
}
__global__ void scatter_kernel(const int* __restrict__ src,
                               const int* __restrict__ dst, int E) {
    int i = blockIdx.x * blockDim.x + threadIdx.x;
    if (i < E) {
        int p = atomicAdd(&g_cur[dst[i]], 1);
        g_srcs[p] = src[i];
    }
}

// ---------------- scores + softmax (needs q,k; normal layout) --------------
__global__ void score_kernel(int n) {
    int dnode = blockIdx.x;
    if (dnode >= n) return;
    int beg = g_off[dnode], end = g_off[dnode + 1];
    __shared__ float4 qs[D / 4];
    __shared__ float sred[4];
    __shared__ float s_m;
    int tid = threadIdx.x, lane = tid & 31, w = tid >> 5;

    qs[tid] = ((const float4*)(g_q + (size_t)dnode * D))[tid];
    __syncthreads();

    float wmax = -3.4e38f;
    for (int e = beg + w; e < end; e += 4) {
        int s = g_srcs[e];
        const float4* kr = (const float4*)(g_k + (size_t)s * D);
        float acc = 0.f;
#pragma unroll
        for (int i = 0; i < 4; i++) {
            float4 kv = kr[lane + 32 * i];
            float4 qv = qs[lane + 32 * i];
            acc += kv.x * qv.x + kv.y * qv.y + kv.z * qv.z + kv.w * qv.w;
        }
        for (int o = 16; o > 0; o >>= 1) acc += __shfl_down_sync(0xffffffffu, acc, o);
        if (lane == 0) {
            g_scores[e] = acc;
            wmax = fmaxf(wmax, acc);
        }
    }
    if (lane == 0) sred[w] = wmax;
    __syncthreads();
    if (tid == 0)
        s_m = fmaxf(fmaxf(sred[0], sred[1]), fmaxf(sred[2], sred[3]));
    __syncthreads();
    float m = s_m;

    float ds = 0.f;
    for (int e = beg + tid; e < end; e += 128) {
        float ex = expf(g_scores[e] - m);
        g_scores[e] = ex;
        ds += ex;
    }
    for (int o = 16; o > 0; o >>= 1) ds += __shfl_down_sync(0xffffffffu, ds, o);
    __syncthreads();
    if (lane == 0) sred[w] = ds;
    __syncthreads();
    if (tid == 0) g_inv[dnode] = 1.f / (sred[0] + sred[1] + sred[2] + sred[3]);
}

// ---------------- aggregate (writes g_attn k-permuted) ---------------------
__global__ void aggregate_kernel(int n) {
    int dnode = blockIdx.x;
    if (dnode >= n) return;
    int beg = g_off[dnode], end = g_off[dnode + 1];
    __shared__ int   s_src[128];
    __shared__ float s_al[128];
    int tid = threadIdx.x;
    float inv = g_inv[dnode];

    float4 a = make_float4(0.f, 0.f, 0.f, 0.f);
    for (int c0 = beg; c0 < end; c0 += 128) {
        int cnt = min(128, end - c0);
        if (tid < cnt) {
            s_src[tid] = g_srcs[c0 + tid];
            s_al[tid] = g_scores[c0 + tid] * inv;
        }
        __syncthreads();
#pragma unroll 4
        for (int j = 0; j < cnt; j++) {
            int s = s_src[j];
            float al = s_al[j];
            float4 v4 = ((const float4*)(g_v + (size_t)s * D))[tid];
            a.x += al * v4.x; a.y += al * v4.y;
            a.z += al * v4.z; a.w += al * v4.w;
        }
        __syncthreads();
    }
    float vs[4] = {f2tf32(a.x), f2tf32(a.y), f2tf32(a.z), f2tf32(a.w)};
    float* drow = g_attn + (size_t)dnode * D;
    int k0 = tid * 4;
#pragma unroll
    for (int c = 0; c < 4; c++) {
        int k = k0 + c;
        drow[(k & ~7) + kperm(k & 7)] = vs[c];
    }
}

// ---------------- launch ----------------
extern "C" void kernel_launch(void* const* d_in, const int* in_sizes, int n_in,
                              void* d_out, int out_size) {
    const float* x  = (const float*)d_in[0];
    const int*   src = (const int*)d_in[1];
    const int*   dst = (const int*)d_in[2];
    const float* Wq = (const float*)d_in[3];
    const float* bq = (const float*)d_in[4];
    const float* Wk = (const float*)d_in[5];
    const float* bk = (const float*)d_in[6];
    const float* Wv = (const float*)d_in[7];
    const float* bv = (const float*)d_in[8];
    const float* Wo = (const float*)d_in[9];
    const float* bo = (const float*)d_in[10];
    float* out = (float*)d_out;

    int n = in_sizes[0] / D;
    int E = in_sizes[1];
    float qscale = 1.f / sqrtf((float)D);

    static cudaStream_t s2 = nullptr;
    static cudaEvent_t evFork = nullptr, evW = nullptr, evJoin = nullptr,
                       evQK = nullptr, evV = nullptr;
    if (!s2) {
        cudaStreamCreateWithFlags(&s2, cudaStreamNonBlocking);
        cudaEventCreateWithFlags(&evFork, cudaEventDisableTiming);
        cudaEventCreateWithFlags(&evW, cudaEventDisableTiming);
        cudaEventCreateWithFlags(&evJoin, cudaEventDisableTiming);
        cudaEventCreateWithFlags(&evQK, cudaEventDisableTiming);
        cudaEventCreateWithFlags(&evV, cudaEventDisableTiming);
    }

    cudaFuncSetAttribute(tgemm_kernel,
                         cudaFuncAttributeMaxDynamicSharedMemorySize, GEMM_SMEM);

    cudaEventRecord(evFork, 0);
    cudaStreamWaitEvent(s2, evFork, 0);

    // side stream: weight conversion + CSR build
    convw_kernel<<<(4 * D * D / 4 + 255) / 256, 256, 0, s2>>>(Wq, Wk, Wv, Wo);
    cudaEventRecord(evW, s2);
    zero_cnt_kernel<<<(n + 255) / 256, 256, 0, s2>>>(n);
    hist_kernel<<<(E + 255) / 256, 256, 0, s2>>>(dst, E);
    scan_kernel<<<1, 1024, 0, s2>>>(n);
    scatter_kernel<<<(E + 255) / 256, 256, 0, s2>>>(src, dst, E);
    cudaEventRecord(evJoin, s2);

    // main: logmap -> QK GEMM
    logmap_kernel<<<n, 128>>>(x, n);
    cudaStreamWaitEvent(0, evW, 0);
    dim3 gqk(8, (n + 127) / 128);
    tgemm_kernel<<<gqk, 256, GEMM_SMEM>>>(bq, bk, bv, 0, n, qscale);
    cudaEventRecord(evQK, 0);

    // side: V GEMM overlaps score kernel on main
    cudaStreamWaitEvent(s2, evQK, 0);
    dim3 gv(4, (n + 127) / 128);
    tgemm_kernel<<<gv, 256, GEMM_SMEM, s2>>>(bq, bk, bv, 2, n, qscale);
    cudaEventRecord(evV, s2);

    // main: scores (needs q,k + CSR) || V GEMM
    cudaStreamWaitEvent(0, evJoin, 0);
    score_kernel<<<n, 128>>>(n);

    // main: aggregate (needs v + scores)
    cudaStreamWaitEvent(0, evV, 0);
    aggregate_kernel<<<n, 128>>>(n);

    dim3 go(4, (n + 127) / 128);
    tgemm_kernel<<<go, 256, GEMM_SMEM>>>(bo, bo, bo, 3, n, 1.f);
    expmap_kernel<<<n, 128>>>(out, n);
}

// round 12
// speedup vs baseline: 1.1320x; 1.1320x over previous
#include <cuda_runtime.h>
#include <cuda_fp16.h>
#include <math.h>
#include <stdint.h>

#define D 512
#define NMAX 20000
#define EMAX 320000

// ---------------- scratch (device globals: allocation-free) ----------------
__device__ float  g_t[NMAX * D];     // tangent vectors, tf32-rounded
__device__ float  g_q[NMAX * D];     // q ; later reused as h
__device__ float  g_k[NMAX * D];
__device__ __half g_vh[NMAX * D];    // v in fp16 (attention pass-3 bytes halved)
__device__ float  g_attn[NMAX * D];  // tf32-rounded at write
__device__ float  g_Wc[4 * D * D];   // tf32-rounded weight copies (q,k,v,o)
__device__ float  g_scores[EMAX];
__device__ int    g_cnt[NMAX];
__device__ int    g_off[NMAX + 1];
__device__ int    g_cur[NMAX];
__device__ int    g_srcs[EMAX];      // src node id in CSR order

__device__ __forceinline__ float f2tf32(float x) {
    uint32_t u;
    asm("cvt.rna.tf32.f32 %0, %1;" : "=r"(u) : "f"(x));
    return __uint_as_float(u);
}

__device__ __forceinline__ void cp_async16(void* sptr, const void* gptr, bool pred) {
    uint32_t sa = (uint32_t)__cvta_generic_to_shared(sptr);
    int sz = pred ? 16 : 0;
    asm volatile("cp.async.cg.shared.global [%0], [%1], 16, %2;\n"
                 :: "r"(sa), "l"(gptr), "r"(sz));
}

// ---------------- W conversion (tf32 round, once per call) -----------------
__global__ void convw_kernel(const float* __restrict__ Wq, const float* __restrict__ Wk,
                             const float* __restrict__ Wv, const float* __restrict__ Wo) {
    int i = blockIdx.x * blockDim.x + threadIdx.x;   // float4 index
    int total = 4 * D * D / 4;
    if (i >= total) return;
    int which = i / (D * D / 4);
    int off = i - which * (D * D / 4);
    const float* src = (which == 0) ? Wq : (which == 1) ? Wk : (which == 2) ? Wv : Wo;
    float4 v = ((const float4*)src)[off];
    v.x = f2tf32(v.x); v.y = f2tf32(v.y); v.z = f2tf32(v.z); v.w = f2tf32(v.w);
    ((float4*)g_Wc)[i] = v;
}

// ---------------- logmap0 (writes tf32-rounded tangent) --------------------
__global__ void logmap_kernel(const float* __restrict__ x, int n) {
    int row = blockIdx.x;
    if (row >= n) return;
    const float4* xr = (const float4*)(x + (size_t)row * D);
    float4 xv = xr[threadIdx.x];
    float ss = xv.x * xv.x + xv.y * xv.y + xv.z * xv.z + xv.w * xv.w;
    for (int o = 16; o > 0; o >>= 1) ss += __shfl_down_sync(0xffffffffu, ss, o);
    __shared__ float sred[4];
    int lane = threadIdx.x & 31, w = threadIdx.x >> 5;
    if (lane == 0) sred[w] = ss;
    __syncthreads();
    float tot = sred[0] + sred[1] + sred[2] + sred[3];
    float nrm = sqrtf(tot);
    float nc = fminf(fmaxf(nrm, 1e-7f), 1.f - 1e-6f);
    float fac = atanhf(nc) / nc;
    float4 o4;
    o4.x = f2tf32(fac * xv.x); o4.y = f2tf32(fac * xv.y);
    o4.z = f2tf32(fac * xv.z); o4.w = f2tf32(fac * xv.w);
    ((float4*)(g_t + (size_t)row * D))[threadIdx.x] = o4;
}

// ---------------- expmap0 (reads g_q as h, writes output) ------------------
__global__ void expmap_kernel(float* __restrict__ out, int n) {
    int row = blockIdx.x;
    if (row >= n) return;
    const float4* hr = (const float4*)(g_q + (size_t)row * D);
    float4 hv = hr[threadIdx.x];
    float ss = hv.x * hv.x + hv.y * hv.y + hv.z * hv.z + hv.w * hv.w;
    for (int o = 16; o > 0; o >>= 1) ss += __shfl_down_sync(0xffffffffu, ss, o);
    __shared__ float sred[4];
    int lane = threadIdx.x & 31, w = threadIdx.x >> 5;
    if (lane == 0) sred[w] = ss;
    __syncthreads();
    float tot = sred[0] + sred[1] + sred[2] + sred[3];
    float nrm = sqrtf(tot);
    float nc = fmaxf(nrm, 1e-7f);
    float fac = tanhf(nc) / nc;
    float4 o4;
    o4.x = fac * hv.x; o4.y = fac * hv.y; o4.z = fac * hv.z; o4.w = fac * hv.w;
    ((float4*)(out + (size_t)row * D))[threadIdx.x] = o4;
}

// ---------------- TF32 tensor-core GEMM (3-stage, 1 barrier/iter) ----------
//   C[M,512] = (A[M,512] @ W[512,512]^T + bias) * scale
// mode 0 (QKV): grid.x = 12, sel = bx>>2 (0/1/2), bn = (bx&3)*128, A = g_t
//   sel==2 (V) writes g_vh as __half2.
// mode 1 (O):   grid.x = 4,  sel = 3, bn = bx*128, A = g_attn, C = g_q
#define SM_STRIDE 36
#define TILE_FLOATS (128 * SM_STRIDE)
#define NSTAGE 3
#define GEMM_SMEM (NSTAGE * 2 * TILE_FLOATS * 4)

__global__ __launch_bounds__(256, 2)
void tgemm_kernel(const float* __restrict__ b0, const float* __restrict__ b1,
                  const float* __restrict__ b2, int mode, int M, float qscale) {
    extern __shared__ float smem[];
    int sel, bn;
    if (mode == 0) { sel = blockIdx.x >> 2; bn = (blockIdx.x & 3) << 7; }
    else           { sel = 3;               bn = blockIdx.x << 7; }
    const float* __restrict__ A = (sel == 3) ? g_attn : g_t;
    const float* __restrict__ W = g_Wc + (size_t)sel * D * D;
    float* __restrict__ C = (sel == 1) ? g_k : g_q;   // sel 2 uses g_vh path
    const float* __restrict__ bias = (sel == 1) ? b1 : (sel == 2) ? b2 : b0;
    float scale = (sel == 0) ? qscale : 1.f;

    int bm = blockIdx.y * 128;
    int tid = threadIdx.x;
    int lane = tid & 31, warp = tid >> 5;
    int wm = (warp >> 2) * 64;
    int wn = (warp & 3) * 32;
    int g = lane >> 2, tg = lane & 3;
    int lrow = tid >> 3, lcol = (tid & 7) << 2;

    float acc[4][4][4];
#pragma unroll
    for (int mt = 0; mt < 4; mt++)
#pragma unroll
        for (int nt = 0; nt < 4; nt++)
#pragma unroll
            for (int i = 0; i < 4; i++) acc[mt][nt][i] = 0.f;

    auto prefetch = [&](int it) {
        float* As = smem + (it % NSTAGE) * 2 * TILE_FLOATS;
        float* Ws = As + TILE_FLOATS;
        int k0 = it * 32;
#pragma unroll
        for (int i = 0; i < 4; i++) {
            int row = lrow + i * 32;
            int ga = bm + row;
            cp_async16(&As[row * SM_STRIDE + lcol],
                       A + (size_t)ga * D + k0 + lcol, ga < M);
            cp_async16(&Ws[row * SM_STRIDE + lcol],
                       W + (size_t)(bn + row) * D + k0 + lcol, true);
        }
        asm volatile("cp.async.commit_group;\n" ::);
    };

    prefetch(0);
    prefetch(1);

    for (int it = 0; it < 16; it++) {
        if (it < 15) {
            asm volatile("cp.async.wait_group 1;\n" ::);
        } else {
            asm volatile("cp.async.wait_group 0;\n" ::);
        }
        __syncthreads();   // all warps done with compute(it-1)
        if (it + 2 < 16) prefetch(it + 2);

        const float* As = smem + (it % NSTAGE) * 2 * TILE_FLOATS;
        const float* Ws = As + TILE_FLOATS;

#pragma unroll
        for (int ks = 0; ks < 4; ks++) {
            int kb = ks * 8;
            uint32_t af[4][4], bf[4][2];
#pragma unroll
            for (int mt = 0; mt < 4; mt++) {
                int r = wm + mt * 16 + g;
                af[mt][0] = __float_as_uint(As[r * SM_STRIDE + kb + tg]);
                af[mt][1] = __float_as_uint(As[(r + 8) * SM_STRIDE + kb + tg]);
                af[mt][2] = __float_as_uint(As[r * SM_STRIDE + kb + tg + 4]);
                af[mt][3] = __float_as_uint(As[(r + 8) * SM_STRIDE + kb + tg + 4]);
            }
#pragma unroll
            for (int nt = 0; nt < 4; nt++) {
                int r = wn + nt * 8 + g;
                bf[nt][0] = __float_as_uint(Ws[r * SM_STRIDE + kb + tg]);
                bf[nt][1] = __float_as_uint(Ws[r * SM_STRIDE + kb + tg + 4]);
            }
#pragma unroll
            for (int mt = 0; mt < 4; mt++)
#pragma unroll
                for (int nt = 0; nt < 4; nt++) {
                    asm volatile(
                        "mma.sync.aligned.m16n8k8.row.col.f32.tf32.tf32.f32 "
                        "{%0,%1,%2,%3}, {%4,%5,%6,%7}, {%8,%9}, {%0,%1,%2,%3};"
                        : "+f"(acc[mt][nt][0]), "+f"(acc[mt][nt][1]),
                          "+f"(acc[mt][nt][2]), "+f"(acc[mt][nt][3])
                        : "r"(af[mt][0]), "r"(af[mt][1]),
                          "r"(af[mt][2]), "r"(af[mt][3]),
                          "r"(bf[nt][0]), "r"(bf[nt][1]));
                }
        }
    }

#pragma unroll
    for (int mt = 0; mt < 4; mt++) {
        int row0 = bm + wm + mt * 16 + g;
#pragma unroll
        for (int nt = 0; nt < 4; nt++) {
            int col = bn + wn + nt * 8 + tg * 2;
            float b0v = bias[col], b1v = bias[col + 1];
            if (sel == 2) {
                // V: store fp16 pairs
                if (row0 < M) {
                    __half2 h = __floats2half2_rn(acc[mt][nt][0] + b0v,
                                                  acc[mt][nt][1] + b1v);
                    *(__half2*)(g_vh + (size_t)row0 * D + col) = h;
                }
                if (row0 + 8 < M) {
                    __half2 h = __floats2half2_rn(acc[mt][nt][2] + b0v,
                                                  acc[mt][nt][3] + b1v);
                    *(__half2*)(g_vh + (size_t)(row0 + 8) * D + col) = h;
                }
            } else {
                if (row0 < M) {
                    float2 o;
                    o.x = (acc[mt][nt][0] + b0v) * scale;
                    o.y = (acc[mt][nt][1] + b1v) * scale;
                    *(float2*)(C + (size_t)row0 * D + col) = o;
                }
                if (row0 + 8 < M) {
                    float2 o;
                    o.x = (acc[mt][nt][2] + b0v) * scale;
                    o.y = (acc[mt][nt][3] + b1v) * scale;
                    *(float2*)(C + (size_t)(row0 + 8) * D + col) = o;
                }
            }
        }
    }
}

// ---------------- CSR build (by dst) ----------------
__global__ void zero_cnt_kernel(int n) {
    int i = blockIdx.x * blockDim.x + threadIdx.x;
    if (i < n) g_cnt[i] = 0;
}
__global__ void hist_kernel(const int* __restrict__ dst, int E) {
    int i = blockIdx.x * blockDim.x + threadIdx.x;
    if (i < E) atomicAdd(&g_cnt[dst[i]], 1);
}
__global__ void scan_kernel(int n) {
    __shared__ int sdata[1024];
    __shared__ int carry_s;
    int t = threadIdx.x;
    if (t == 0) carry_s = 0;
    __syncthreads();
    for (int base = 0; base < n; base += 1024) {
        int idx = base + t;
        int v = (idx < n) ? g_cnt[idx] : 0;
        sdata[t] = v;
        __syncthreads();
        for (int off = 1; off < 1024; off <<= 1) {
            int tmp = (t >= off) ? sdata[t - off] : 0;
            __syncthreads();
            sdata[t] += tmp;
            __syncthreads();
        }
        int incl = sdata[t];
        int carry = carry_s;
        if (idx < n) {
            int excl = carry + incl - v;
            g_off[idx] = excl;
            g_cur[idx] = excl;
        }
        __syncthreads();
        if (t == 1023) carry_s = carry + incl;
        __syncthreads();
    }
    if (t == 0) g_off[n] = carry_s;
}
__global__ void scatter_kernel(const int* __restrict__ src,
                               const int* __restrict__ dst, int E) {
    int i = blockIdx.x * blockDim.x + threadIdx.x;
    if (i < E) {
        int p = atomicAdd(&g_cur[dst[i]], 1);
        g_srcs[p] = src[i];
    }
}

// ---------------- fused per-dst attention (128 threads) --------------------
__global__ void attn_kernel(int n) {
    int dnode = blockIdx.x;
    if (dnode >= n) return;
    int beg = g_off[dnode], end = g_off[dnode + 1];
    __shared__ float4 qs[D / 4];
    __shared__ float sred[4];
    __shared__ float s_m, s_inv;
    __shared__ int   s_src[128];
    __shared__ float s_al[128];
    int tid = threadIdx.x, lane = tid & 31, w = tid >> 5;

    qs[tid] = ((const float4*)(g_q + (size_t)dnode * D))[tid];
    __syncthreads();

    // pass 1: scores + block max (warp per edge, float4 dots, k in fp32)
    float wmax = -3.4e38f;
    for (int e = beg + w; e < end; e += 4) {
        int s = g_srcs[e];
        const float4* kr = (const float4*)(g_k + (size_t)s * D);
        float acc = 0.f;
#pragma unroll
        for (int i = 0; i < 4; i++) {
            float4 kv = kr[lane + 32 * i];
            float4 qv = qs[lane + 32 * i];
            acc += kv.x * qv.x + kv.y * qv.y + kv.z * qv.z + kv.w * qv.w;
        }
        for (int o = 16; o > 0; o >>= 1) acc += __shfl_down_sync(0xffffffffu, acc, o);
        if (lane == 0) {
            g_scores[e] = acc;
            wmax = fmaxf(wmax, acc);
        }
    }
    if (lane == 0) sred[w] = wmax;
    __syncthreads();
    if (tid == 0)
        s_m = fmaxf(fmaxf(sred[0], sred[1]), fmaxf(sred[2], sred[3]));
    __syncthreads();
    float m = s_m;

    // pass 2: exp + denom
    float ds = 0.f;
    for (int e = beg + tid; e < end; e += 128) {
        float ex = expf(g_scores[e] - m);
        g_scores[e] = ex;
        ds += ex;
    }
    for (int o = 16; o > 0; o >>= 1) ds += __shfl_down_sync(0xffffffffu, ds, o);
    __syncthreads();
    if (lane == 0) sred[w] = ds;
    __syncthreads();
    if (tid == 0) s_inv = 1.f / (sred[0] + sred[1] + sred[2] + sred[3]);
    __syncthreads();
    float inv = s_inv;

    // pass 3: thread owns 4 cols; v rows are fp16 (uint2 = 4 halves / edge)
    float4 a = make_float4(0.f, 0.f, 0.f, 0.f);
    for (int c0 = beg; c0 < end; c0 += 128) {
        int cnt = min(128, end - c0);
        if (tid < cnt) {
            s_src[tid] = g_srcs[c0 + tid];
            s_al[tid] = g_scores[c0 + tid] * inv;
        }
        __syncthreads();
#pragma unroll 4
        for (int j = 0; j < cnt; j++) {
            int s = s_src[j];
            float al = s_al[j];
            uint2 raw = ((const uint2*)(g_vh + (size_t)s * D))[tid];
            __half2 h0 = *reinterpret_cast<__half2*>(&raw.x);
            __half2 h1 = *reinterpret_cast<__half2*>(&raw.y);
            float2 f0 = __half22float2(h0);
            float2 f1 = __half22float2(h1);
            a.x += al * f0.x; a.y += al * f0.y;
            a.z += al * f1.x; a.w += al * f1.y;
        }
        __syncthreads();
    }
    float4 o4;
    o4.x = f2tf32(a.x); o4.y = f2tf32(a.y);
    o4.z = f2tf32(a.z); o4.w = f2tf32(a.w);
    ((float4*)(g_attn + (size_t)dnode * D))[tid] = o4;
}

// ---------------- launch ----------------
extern "C" void kernel_launch(void* const* d_in, const int* in_sizes, int n_in,
                              void* d_out, int out_size) {
    const float* x  = (const float*)d_in[0];
    const int*   src = (const int*)d_in[1];
    const int*   dst = (const int*)d_in[2];
    const float* Wq = (const float*)d_in[3];
    const float* bq = (const float*)d_in[4];
    const float* Wk = (const float*)d_in[5];
    const float* bk = (const float*)d_in[6];
    const float* Wv = (const float*)d_in[7];
    const float* bv = (const float*)d_in[8];
    const float* Wo = (const float*)d_in[9];
    const float* bo = (const float*)d_in[10];
    float* out = (float*)d_out;

    int n = in_sizes[0] / D;
    int E = in_sizes[1];
    float qscale = 1.f / sqrtf((float)D);

    static cudaStream_t s2 = nullptr;
    static cudaEvent_t evFork = nullptr, evW = nullptr, evJoin = nullptr;
    if (!s2) {
        cudaStreamCreateWithFlags(&s2, cudaStreamNonBlocking);
        cudaEventCreateWithFlags(&evFork, cudaEventDisableTiming);
        cudaEventCreateWithFlags(&evW, cudaEventDisableTiming);
        cudaEventCreateWithFlags(&evJoin, cudaEventDisableTiming);
    }

    cudaFuncSetAttribute(tgemm_kernel,
                         cudaFuncAttributeMaxDynamicSharedMemorySize, GEMM_SMEM);

    cudaEventRecord(evFork, 0);
    cudaStreamWaitEvent(s2, evFork, 0);

    convw_kernel<<<(4 * D * D / 4 + 255) / 256, 256, 0, s2>>>(Wq, Wk, Wv, Wo);
    cudaEventRecord(evW, s2);
    zero_cnt_kernel<<<(n + 255) / 256, 256, 0, s2>>>(n);
    hist_kernel<<<(E + 255) / 256, 256, 0, s2>>>(dst, E);
    scan_kernel<<<1, 1024, 0, s2>>>(n);
    scatter_kernel<<<(E + 255) / 256, 256, 0, s2>>>(src, dst, E);
    cudaEventRecord(evJoin, s2);

    logmap_kernel<<<n, 128>>>(x, n);
    cudaStreamWaitEvent(0, evW, 0);

    dim3 gqkv(12, (n + 127) / 128);
    tgemm_kernel<<<gqkv, 256, GEMM_SMEM>>>(bq, bk, bv, 0, n, qscale);

    cudaStreamWaitEvent(0, evJoin, 0);
    attn_kernel<<<n, 128>>>(n);

    dim3 go(4, (n + 127) / 128);
    tgemm_kernel<<<go, 256, GEMM_SMEM>>>(bo, bo, bo, 1, n, 1.f);
    expmap_kernel<<<n, 128>>>(out, n);
}

// round 13
// speedup vs baseline: 1.1425x; 1.0092x over previous
#include <cuda_runtime.h>
#include <cuda_fp16.h>
#include <math.h>
#include <stdint.h>

#define D 512
#define NMAX 20000
#define EMAX 320000

// ---------------- scratch (device globals: allocation-free) ----------------
__device__ float  g_t[NMAX * D];     // tangent vectors, tf32-rounded
__device__ float  g_q[NMAX * D];     // q ; later reused as h
__device__ float  g_k[NMAX * D];
__device__ __half g_vh[NMAX * D];    // v in fp16
__device__ float  g_attn[NMAX * D];  // tf32-rounded at write
__device__ float  g_Wc[4 * D * D];   // tf32-rounded weight copies (q,k,v,o)
__device__ float  g_scores[EMAX];
__device__ int    g_cnt[NMAX];
__device__ int    g_off[NMAX + 1];
__device__ int    g_cur[NMAX];
__device__ int    g_srcs[EMAX];      // src node id in CSR order

__device__ __forceinline__ float f2tf32(float x) {
    uint32_t u;
    asm("cvt.rna.tf32.f32 %0, %1;" : "=r"(u) : "f"(x));
    return __uint_as_float(u);
}

__device__ __forceinline__ void cp_async16(void* sptr, const void* gptr, bool pred) {
    uint32_t sa = (uint32_t)__cvta_generic_to_shared(sptr);
    int sz = pred ? 16 : 0;
    asm volatile("cp.async.cg.shared.global [%0], [%1], 16, %2;\n"
                 :: "r"(sa), "l"(gptr), "r"(sz));
}

// ---------------- W conversion (tf32 round, once per call) -----------------
__global__ void convw_kernel(const float* __restrict__ Wq, const float* __restrict__ Wk,
                             const float* __restrict__ Wv, const float* __restrict__ Wo) {
    int i = blockIdx.x * blockDim.x + threadIdx.x;   // float4 index
    int total = 4 * D * D / 4;
    if (i >= total) return;
    int which = i / (D * D / 4);
    int off = i - which * (D * D / 4);
    const float* src = (which == 0) ? Wq : (which == 1) ? Wk : (which == 2) ? Wv : Wo;
    float4 v = ((const float4*)src)[off];
    v.x = f2tf32(v.x); v.y = f2tf32(v.y); v.z = f2tf32(v.z); v.w = f2tf32(v.w);
    ((float4*)g_Wc)[i] = v;
}

// ---------------- logmap0 (writes tf32-rounded tangent) --------------------
__global__ void logmap_kernel(const float* __restrict__ x, int n) {
    int row = blockIdx.x;
    if (row >= n) return;
    const float4* xr = (const float4*)(x + (size_t)row * D);
    float4 xv = xr[threadIdx.x];
    float ss = xv.x * xv.x + xv.y * xv.y + xv.z * xv.z + xv.w * xv.w;
    for (int o = 16; o > 0; o >>= 1) ss += __shfl_down_sync(0xffffffffu, ss, o);
    __shared__ float sred[4];
    int lane = threadIdx.x & 31, w = threadIdx.x >> 5;
    if (lane == 0) sred[w] = ss;
    __syncthreads();
    float tot = sred[0] + sred[1] + sred[2] + sred[3];
    float nrm = sqrtf(tot);
    float nc = fminf(fmaxf(nrm, 1e-7f), 1.f - 1e-6f);
    float fac = atanhf(nc) / nc;
    float4 o4;
    o4.x = f2tf32(fac * xv.x); o4.y = f2tf32(fac * xv.y);
    o4.z = f2tf32(fac * xv.z); o4.w = f2tf32(fac * xv.w);
    ((float4*)(g_t + (size_t)row * D))[threadIdx.x] = o4;
}

// ---------------- expmap0 (reads g_q as h, writes output) ------------------
__global__ void expmap_kernel(float* __restrict__ out, int n) {
    int row = blockIdx.x;
    if (row >= n) return;
    const float4* hr = (const float4*)(g_q + (size_t)row * D);
    float4 hv = hr[threadIdx.x];
    float ss = hv.x * hv.x + hv.y * hv.y + hv.z * hv.z + hv.w * hv.w;
    for (int o = 16; o > 0; o >>= 1) ss += __shfl_down_sync(0xffffffffu, ss, o);
    __shared__ float sred[4];
    int lane = threadIdx.x & 31, w = threadIdx.x >> 5;
    if (lane == 0) sred[w] = ss;
    __syncthreads();
    float tot = sred[0] + sred[1] + sred[2] + sred[3];
    float nrm = sqrtf(tot);
    float nc = fmaxf(nrm, 1e-7f);
    float fac = tanhf(nc) / nc;
    float4 o4;
    o4.x = fac * hv.x; o4.y = fac * hv.y; o4.z = fac * hv.z; o4.w = fac * hv.w;
    ((float4*)(out + (size_t)row * D))[threadIdx.x] = o4;
}

// ---------------- TF32 tensor-core GEMM (3-stage, 1 barrier/iter) ----------
//   C[M,512] = (A[M,512] @ W[512,512]^T + bias) * scale
// mode 0 (QKV): grid.x = 12, sel = bx>>2 (0/1/2), bn = (bx&3)*128, A = g_t
//   sel==2 (V) writes g_vh as __half2.
// mode 1 (O):   grid.x = 4,  sel = 3, bn = bx*128, A = g_attn, C = g_q
#define SM_STRIDE 36
#define TILE_FLOATS (128 * SM_STRIDE)
#define NSTAGE 3
#define GEMM_SMEM (NSTAGE * 2 * TILE_FLOATS * 4)

__global__ __launch_bounds__(256, 2)
void tgemm_kernel(const float* __restrict__ b0, const float* __restrict__ b1,
                  const float* __restrict__ b2, int mode, int M, float qscale) {
    extern __shared__ float smem[];
    int sel, bn;
    if (mode == 0) { sel = blockIdx.x >> 2; bn = (blockIdx.x & 3) << 7; }
    else           { sel = 3;               bn = blockIdx.x << 7; }
    const float* __restrict__ A = (sel == 3) ? g_attn : g_t;
    const float* __restrict__ W = g_Wc + (size_t)sel * D * D;
    float* __restrict__ C = (sel == 1) ? g_k : g_q;   // sel 2 uses g_vh path
    const float* __restrict__ bias = (sel == 1) ? b1 : (sel == 2) ? b2 : b0;
    float scale = (sel == 0) ? qscale : 1.f;

    int bm = blockIdx.y * 128;
    int tid = threadIdx.x;
    int lane = tid & 31, warp = tid >> 5;
    int wm = (warp >> 2) * 64;
    int wn = (warp & 3) * 32;
    int g = lane >> 2, tg = lane & 3;
    int lrow = tid >> 3, lcol = (tid & 7) << 2;

    float acc[4][4][4];
#pragma unroll
    for (int mt = 0; mt < 4; mt++)
#pragma unroll
        for (int nt = 0; nt < 4; nt++)
#pragma unroll
            for (int i = 0; i < 4; i++) acc[mt][nt][i] = 0.f;

    auto prefetch = [&](int it) {
        float* As = smem + (it % NSTAGE) * 2 * TILE_FLOATS;
        float* Ws = As + TILE_FLOATS;
        int k0 = it * 32;
#pragma unroll
        for (int i = 0; i < 4; i++) {
            int row = lrow + i * 32;
            int ga = bm + row;
            cp_async16(&As[row * SM_STRIDE + lcol],
                       A + (size_t)ga * D + k0 + lcol, ga < M);
            cp_async16(&Ws[row * SM_STRIDE + lcol],
                       W + (size_t)(bn + row) * D + k0 + lcol, true);
        }
        asm volatile("cp.async.commit_group;\n" ::);
    };

    prefetch(0);
    prefetch(1);

    for (int it = 0; it < 16; it++) {
        if (it < 15) {
            asm volatile("cp.async.wait_group 1;\n" ::);
        } else {
            asm volatile("cp.async.wait_group 0;\n" ::);
        }
        __syncthreads();
        if (it + 2 < 16) prefetch(it + 2);

        const float* As = smem + (it % NSTAGE) * 2 * TILE_FLOATS;
        const float* Ws = As + TILE_FLOATS;

#pragma unroll
        for (int ks = 0; ks < 4; ks++) {
            int kb = ks * 8;
            uint32_t af[4][4], bf[4][2];
#pragma unroll
            for (int mt = 0; mt < 4; mt++) {
                int r = wm + mt * 16 + g;
                af[mt][0] = __float_as_uint(As[r * SM_STRIDE + kb + tg]);
                af[mt][1] = __float_as_uint(As[(r + 8) * SM_STRIDE + kb + tg]);
                af[mt][2] = __float_as_uint(As[r * SM_STRIDE + kb + tg + 4]);
                af[mt][3] = __float_as_uint(As[(r + 8) * SM_STRIDE + kb + tg + 4]);
            }
#pragma unroll
            for (int nt = 0; nt < 4; nt++) {
                int r = wn + nt * 8 + g;
                bf[nt][0] = __float_as_uint(Ws[r * SM_STRIDE + kb + tg]);
                bf[nt][1] = __float_as_uint(Ws[r * SM_STRIDE + kb + tg + 4]);
            }
#pragma unroll
            for (int mt = 0; mt < 4; mt++)
#pragma unroll
                for (int nt = 0; nt < 4; nt++) {
                    asm volatile(
                        "mma.sync.aligned.m16n8k8.row.col.f32.tf32.tf32.f32 "
                        "{%0,%1,%2,%3}, {%4,%5,%6,%7}, {%8,%9}, {%0,%1,%2,%3};"
                        : "+f"(acc[mt][nt][0]), "+f"(acc[mt][nt][1]),
                          "+f"(acc[mt][nt][2]), "+f"(acc[mt][nt][3])
                        : "r"(af[mt][0]), "r"(af[mt][1]),
                          "r"(af[mt][2]), "r"(af[mt][3]),
                          "r"(bf[nt][0]), "r"(bf[nt][1]));
                }
        }
    }

#pragma unroll
    for (int mt = 0; mt < 4; mt++) {
        int row0 = bm + wm + mt * 16 + g;
#pragma unroll
        for (int nt = 0; nt < 4; nt++) {
            int col = bn + wn + nt * 8 + tg * 2;
            float b0v = bias[col], b1v = bias[col + 1];
            if (sel == 2) {
                if (row0 < M) {
                    __half2 h = __floats2half2_rn(acc[mt][nt][0] + b0v,
                                                  acc[mt][nt][1] + b1v);
                    *(__half2*)(g_vh + (size_t)row0 * D + col) = h;
                }
                if (row0 + 8 < M) {
                    __half2 h = __floats2half2_rn(acc[mt][nt][2] + b0v,
                                                  acc[mt][nt][3] + b1v);
                    *(__half2*)(g_vh + (size_t)(row0 + 8) * D + col) = h;
                }
            } else {
                if (row0 < M) {
                    float2 o;
                    o.x = (acc[mt][nt][0] + b0v) * scale;
                    o.y = (acc[mt][nt][1] + b1v) * scale;
                    *(float2*)(C + (size_t)row0 * D + col) = o;
                }
                if (row0 + 8 < M) {
                    float2 o;
                    o.x = (acc[mt][nt][2] + b0v) * scale;
                    o.y = (acc[mt][nt][3] + b1v) * scale;
                    *(float2*)(C + (size_t)(row0 + 8) * D + col) = o;
                }
            }
        }
    }
}

// ---------------- CSR build (by dst) ----------------
__global__ void zero_cnt_kernel(int n) {
    int i = blockIdx.x * blockDim.x + threadIdx.x;
    if (i < n) g_cnt[i] = 0;
}
__global__ void hist_kernel(const int* __restrict__ dst, int E) {
    int i = blockIdx.x * blockDim.x + threadIdx.x;
    if (i < E) atomicAdd(&g_cnt[dst[i]], 1);
}
__global__ void scan_kernel(int n) {
    __shared__ int sdata[1024];
    __shared__ int carry_s;
    int t = threadIdx.x;
    if (t == 0) carry_s = 0;
    __syncthreads();
    for (int base = 0; base < n; base += 1024) {
        int idx = base + t;
        int v = (idx < n) ? g_cnt[idx] : 0;
        sdata[t] = v;
        __syncthreads();
        for (int off = 1; off < 1024; off <<= 1) {
            int tmp = (t >= off) ? sdata[t - off] : 0;
            __syncthreads();
            sdata[t] += tmp;
            __syncthreads();
        }
        int incl = sdata[t];
        int carry = carry_s;
        if (idx < n) {
            int excl = carry + incl - v;
            g_off[idx] = excl;
            g_cur[idx] = excl;
        }
        __syncthreads();
        if (t == 1023) carry_s = carry + incl;
        __syncthreads();
    }
    if (t == 0) g_off[n] = carry_s;
}
__global__ void scatter_kernel(const int* __restrict__ src,
                               const int* __restrict__ dst, int E) {
    int i = blockIdx.x * blockDim.x + threadIdx.x;
    if (i < E) {
        int p = atomicAdd(&g_cur[dst[i]], 1);
        g_srcs[p] = src[i];
    }
}

// ---------------- warp-per-dst attention (no smem, no block barriers) ------
// 8 warps/block, one dst per warp. Scores live in per-lane register slots
// (up to 128 edges per dst; avg degree is 16, Poisson max ~45).
__global__ __launch_bounds__(256)
void attn_kernel(int n) {
    const unsigned FULL = 0xffffffffu;
    int lane = threadIdx.x & 31;
    int dnode = blockIdx.x * 8 + (threadIdx.x >> 5);
    if (dnode >= n) return;
    int beg = g_off[dnode], deg = g_off[dnode + 1] - beg;

    // q row in registers: q4[i] = row[lane + 32*i]
    const float4* qr = (const float4*)(g_q + (size_t)dnode * D);
    float4 q4[4];
#pragma unroll
    for (int i = 0; i < 4; i++) q4[i] = qr[lane + 32 * i];

    // pass 1: one edge at a time, whole-warp dot; score owned by lane idx&31
    float sc[4];
    float wmax = -3.4e38f;
    for (int idx = 0; idx < deg; idx++) {
        int s = g_srcs[beg + idx];          // broadcast load
        const float4* kr = (const float4*)(g_k + (size_t)s * D);
        float acc = 0.f;
#pragma unroll
        for (int i = 0; i < 4; i++) {
            float4 kv = kr[lane + 32 * i];
            acc += kv.x * q4[i].x + kv.y * q4[i].y
                 + kv.z * q4[i].z + kv.w * q4[i].w;
        }
#pragma unroll
        for (int o = 16; o > 0; o >>= 1)
            acc += __shfl_down_sync(FULL, acc, o);
        acc = __shfl_sync(FULL, acc, 0);    // broadcast score
        if ((idx & 31) == lane) sc[idx >> 5] = acc;
        wmax = fmaxf(wmax, acc);
    }

    // pass 2: exp + denom (per-lane slots, warp reduce)
    float ex[4];
    float ds = 0.f;
#pragma unroll
    for (int slot = 0; slot < 4; slot++) {
        int idx = slot * 32 + lane;
        if (idx < deg) { ex[slot] = expf(sc[slot] - wmax); ds += ex[slot]; }
        else ex[slot] = 0.f;
    }
#pragma unroll
    for (int o = 16; o > 0; o >>= 1)
        ds += __shfl_down_sync(FULL, ds, o);
    ds = __shfl_sync(FULL, ds, 0);
    float inv = 1.f / ds;

    // pass 3: accumulate fp16 v rows; lane owns halves [8l..8l+7],[256+8l..]
    float a[16];
#pragma unroll
    for (int i = 0; i < 16; i++) a[i] = 0.f;
    for (int idx = 0; idx < deg; idx++) {
        float al = __shfl_sync(FULL, ex[idx >> 5], idx & 31) * inv;
        int s = g_srcs[beg + idx];
        const uint4* vr = (const uint4*)(g_vh + (size_t)s * D);
        uint4 r0 = vr[lane];
        uint4 r1 = vr[lane + 32];
        const __half2* h0 = (const __half2*)&r0;
        const __half2* h1 = (const __half2*)&r1;
#pragma unroll
        for (int j = 0; j < 4; j++) {
            float2 f0 = __half22float2(h0[j]);
            float2 f1 = __half22float2(h1[j]);
            a[2 * j + 0] += al * f0.x;
            a[2 * j + 1] += al * f0.y;
            a[8 + 2 * j + 0] += al * f1.x;
            a[8 + 2 * j + 1] += al * f1.y;
        }
    }

    // writeback (tf32-rounded): halves 8l..8l+7 -> float4 pair at lane*2
    float* arow = g_attn + (size_t)dnode * D;
    float4 o0 = make_float4(f2tf32(a[0]), f2tf32(a[1]), f2tf32(a[2]), f2tf32(a[3]));
    float4 o1 = make_float4(f2tf32(a[4]), f2tf32(a[5]), f2tf32(a[6]), f2tf32(a[7]));
    float4 o2 = make_float4(f2tf32(a[8]), f2tf32(a[9]), f2tf32(a[10]), f2tf32(a[11]));
    float4 o3 = make_float4(f2tf32(a[12]), f2tf32(a[13]), f2tf32(a[14]), f2tf32(a[15]));
    ((float4*)arow)[lane * 2 + 0] = o0;
    ((float4*)arow)[lane * 2 + 1] = o1;
    ((float4*)(arow + 256))[lane * 2 + 0] = o2;
    ((float4*)(arow + 256))[lane * 2 + 1] = o3;
}

// ---------------- launch ----------------
extern "C" void kernel_launch(void* const* d_in, const int* in_sizes, int n_in,
                              void* d_out, int out_size) {
    const float* x  = (const float*)d_in[0];
    const int*   src = (const int*)d_in[1];
    const int*   dst = (const int*)d_in[2];
    const float* Wq = (const float*)d_in[3];
    const float* bq = (const float*)d_in[4];
    const float* Wk = (const float*)d_in[5];
    const float* bk = (const float*)d_in[6];
    const float* Wv = (const float*)d_in[7];
    const float* bv = (const float*)d_in[8];
    const float* Wo = (const float*)d_in[9];
    const float* bo = (const float*)d_in[10];
    float* out = (float*)d_out;

    int n = in_sizes[0] / D;
    int E = in_sizes[1];
    float qscale = 1.f / sqrtf((float)D);

    static cudaStream_t s2 = nullptr;
    static cudaEvent_t evFork = nullptr, evW = nullptr, evJoin = nullptr;
    if (!s2) {
        cudaStreamCreateWithFlags(&s2, cudaStreamNonBlocking);
        cudaEventCreateWithFlags(&evFork, cudaEventDisableTiming);
        cudaEventCreateWithFlags(&evW, cudaEventDisableTiming);
        cudaEventCreateWithFlags(&evJoin, cudaEventDisableTiming);
    }

    cudaFuncSetAttribute(tgemm_kernel,
                         cudaFuncAttributeMaxDynamicSharedMemorySize, GEMM_SMEM);

    cudaEventRecord(evFork, 0);
    cudaStreamWaitEvent(s2, evFork, 0);

    convw_kernel<<<(4 * D * D / 4 + 255) / 256, 256, 0, s2>>>(Wq, Wk, Wv, Wo);
    cudaEventRecord(evW, s2);
    zero_cnt_kernel<<<(n + 255) / 256, 256, 0, s2>>>(n);
    hist_kernel<<<(E + 255) / 256, 256, 0, s2>>>(dst, E);
    scan_kernel<<<1, 1024, 0, s2>>>(n);
    scatter_kernel<<<(E + 255) / 256, 256, 0, s2>>>(src, dst, E);
    cudaEventRecord(evJoin, s2);

    logmap_kernel<<<n, 128>>>(x, n);
    cudaStreamWaitEvent(0, evW, 0);

    dim3 gqkv(12, (n + 127) / 128);
    tgemm_kernel<<<gqkv, 256, GEMM_SMEM>>>(bq, bk, bv, 0, n, qscale);

    cudaStreamWaitEvent(0, evJoin, 0);
    attn_kernel<<<(n + 7) / 8, 256>>>(n);

    dim3 go(4, (n + 127) / 128);
    tgemm_kernel<<<go, 256, GEMM_SMEM>>>(bo, bo, bo, 1, n, 1.f);
    expmap_kernel<<<n, 128>>>(out, n);
}

// round 14
// speedup vs baseline: 1.4964x; 1.3098x over previous
#include <cuda_runtime.h>
#include <cuda_fp16.h>
#include <math.h>
#include <stdint.h>

#define D 512
#define NMAX 20000
#define EMAX 320000

// ---------------- scratch (device globals: allocation-free) ----------------
__device__ __half g_th[NMAX * D];    // tangent vectors, fp16
__device__ float  g_q[NMAX * D];     // q (fp32; attention reads it)
__device__ float  g_k[NMAX * D];     // k (fp32; attention reads it)
__device__ __half g_vh[NMAX * D];    // v (fp16; attention pass 3)
__device__ __half g_ah[NMAX * D];    // attn output, fp16 (O-GEMM input)
__device__ __half g_Wh[4 * D * D];   // fp16 weight copies (q,k,v,o)
__device__ float  g_scores[EMAX];
__device__ int    g_cnt[NMAX];
__device__ int    g_off[NMAX + 1];
__device__ int    g_cur[NMAX];
__device__ int    g_srcs[EMAX];      // src node id in CSR order

__device__ __forceinline__ void cp_async16(void* sptr, const void* gptr, bool pred) {
    uint32_t sa = (uint32_t)__cvta_generic_to_shared(sptr);
    int sz = pred ? 16 : 0;
    asm volatile("cp.async.cg.shared.global [%0], [%1], 16, %2;\n"
                 :: "r"(sa), "l"(gptr), "r"(sz));
}

__device__ __forceinline__ uint32_t h2bits(__half2 h) {
    return *reinterpret_cast<uint32_t*>(&h);
}

// ---------------- W conversion (fp16 round, once per call) -----------------
__global__ void convw_kernel(const float* __restrict__ Wq, const float* __restrict__ Wk,
                             const float* __restrict__ Wv, const float* __restrict__ Wo) {
    int i = blockIdx.x * blockDim.x + threadIdx.x;   // float4 index
    int total = 4 * D * D / 4;
    if (i >= total) return;
    int which = i / (D * D / 4);
    int off = i - which * (D * D / 4);
    const float* src = (which == 0) ? Wq : (which == 1) ? Wk : (which == 2) ? Wv : Wo;
    float4 v = ((const float4*)src)[off];
    uint2 o;
    o.x = h2bits(__floats2half2_rn(v.x, v.y));
    o.y = h2bits(__floats2half2_rn(v.z, v.w));
    ((uint2*)(g_Wh + (size_t)which * D * D))[off] = o;
}

// ---------------- logmap0 (writes fp16 tangent) ----------------------------
__global__ void logmap_kernel(const float* __restrict__ x, int n) {
    int row = blockIdx.x;
    if (row >= n) return;
    const float4* xr = (const float4*)(x + (size_t)row * D);
    float4 xv = xr[threadIdx.x];
    float ss = xv.x * xv.x + xv.y * xv.y + xv.z * xv.z + xv.w * xv.w;
    for (int o = 16; o > 0; o >>= 1) ss += __shfl_down_sync(0xffffffffu, ss, o);
    __shared__ float sred[4];
    int lane = threadIdx.x & 31, w = threadIdx.x >> 5;
    if (lane == 0) sred[w] = ss;
    __syncthreads();
    float tot = sred[0] + sred[1] + sred[2] + sred[3];
    float nrm = sqrtf(tot);
    float nc = fminf(fmaxf(nrm, 1e-7f), 1.f - 1e-6f);
    float fac = atanhf(nc) / nc;
    uint2 o;
    o.x = h2bits(__floats2half2_rn(fac * xv.x, fac * xv.y));
    o.y = h2bits(__floats2half2_rn(fac * xv.z, fac * xv.w));
    ((uint2*)(g_th + (size_t)row * D))[threadIdx.x] = o;
}

// ---------------- expmap0 (reads g_q as h, writes output) ------------------
__global__ void expmap_kernel(float* __restrict__ out, int n) {
    int row = blockIdx.x;
    if (row >= n) return;
    const float4* hr = (const float4*)(g_q + (size_t)row * D);
    float4 hv = hr[threadIdx.x];
    float ss = hv.x * hv.x + hv.y * hv.y + hv.z * hv.z + hv.w * hv.w;
    for (int o = 16; o > 0; o >>= 1) ss += __shfl_down_sync(0xffffffffu, ss, o);
    __shared__ float sred[4];
    int lane = threadIdx.x & 31, w = threadIdx.x >> 5;
    if (lane == 0) sred[w] = ss;
    __syncthreads();
    float tot = sred[0] + sred[1] + sred[2] + sred[3];
    float nrm = sqrtf(tot);
    float nc = fmaxf(nrm, 1e-7f);
    float fac = tanhf(nc) / nc;
    float4 o4;
    o4.x = fac * hv.x; o4.y = fac * hv.y; o4.z = fac * hv.z; o4.w = fac * hv.w;
    ((float4*)(out + (size_t)row * D))[threadIdx.x] = o4;
}

// ---------------- FP16 tensor-core GEMM (3-stage, m16n8k16) ----------------
//   C[M,512] = (A[M,512] @ W[512,512]^T + bias) * scale ; fp32 accumulate
// mode 0 (QKV): grid.x = 12, sel = bx>>2 (0/1/2), bn = (bx&3)*128, A = g_th
//   sel==2 (V) writes g_vh as __half2.
// mode 1 (O):   grid.x = 4,  sel = 3, bn = bx*128, A = g_ah, C = g_q
// smem row stride 40 halves (80 B): fragment word idx = 20r + tg (+4)
//   -> banks (20g+tg) mod 32 all-distinct across the warp: conflict-free.
#define HSTRIDE 40
#define WSTRIDE 20
#define TILE_HALFS (128 * HSTRIDE)
#define NSTAGE 3
#define GEMM_SMEM (NSTAGE * 2 * TILE_HALFS * 2)   // 61440 bytes

__global__ __launch_bounds__(256, 2)
void tgemm_kernel(const float* __restrict__ b0, const float* __restrict__ b1,
                  const float* __restrict__ b2, int mode, int M, float qscale) {
    extern __shared__ __half smem_h[];
    int sel, bn;
    if (mode == 0) { sel = blockIdx.x >> 2; bn = (blockIdx.x & 3) << 7; }
    else           { sel = 3;               bn = blockIdx.x << 7; }
    const __half* __restrict__ A = (sel == 3) ? g_ah : g_th;
    const __half* __restrict__ W = g_Wh + (size_t)sel * D * D;
    float* __restrict__ C = (sel == 1) ? g_k : g_q;   // sel 2 uses g_vh path
    const float* __restrict__ bias = (sel == 1) ? b1 : (sel == 2) ? b2 : b0;
    float scale = (sel == 0) ? qscale : 1.f;

    int bm = blockIdx.y * 128;
    int tid = threadIdx.x;
    int lane = tid & 31, warp = tid >> 5;
    int wm = (warp >> 2) * 64;
    int wn = (warp & 3) * 32;
    int g = lane >> 2, tg = lane & 3;

    float acc[4][4][4];
#pragma unroll
    for (int mt = 0; mt < 4; mt++)
#pragma unroll
        for (int nt = 0; nt < 4; nt++)
#pragma unroll
            for (int i = 0; i < 4; i++) acc[mt][nt][i] = 0.f;

    auto prefetch = [&](int it) {
        __half* As = smem_h + (it % NSTAGE) * 2 * TILE_HALFS;
        __half* Ws = As + TILE_HALFS;
        int k0 = it * 32;
#pragma unroll
        for (int i = 0; i < 2; i++) {
            int ci = tid + i * 256;           // 512 chunks of 16B per matrix
            int row = ci >> 2, col8 = (ci & 3) * 8;
            int ga = bm + row;
            cp_async16(&As[row * HSTRIDE + col8],
                       A + (size_t)ga * D + k0 + col8, ga < M);
            cp_async16(&Ws[row * HSTRIDE + col8],
                       W + (size_t)(bn + row) * D + k0 + col8, true);
        }
        asm volatile("cp.async.commit_group;\n" ::);
    };

    prefetch(0);
    prefetch(1);

    for (int it = 0; it < 16; it++) {
        if (it < 15) {
            asm volatile("cp.async.wait_group 1;\n" ::);
        } else {
            asm volatile("cp.async.wait_group 0;\n" ::);
        }
        __syncthreads();
        if (it + 2 < 16) prefetch(it + 2);

        const uint32_t* Asw = (const uint32_t*)(smem_h + (it % NSTAGE) * 2 * TILE_HALFS);
        const uint32_t* Wsw = Asw + TILE_HALFS / 2;

#pragma unroll
        for (int ks = 0; ks < 2; ks++) {
            int kw = ks * 8;                  // word offset of this k16 step
            uint32_t af[4][4], bf[4][2];
#pragma unroll
            for (int mt = 0; mt < 4; mt++) {
                int r = wm + mt * 16 + g;
                af[mt][0] = Asw[r * WSTRIDE + kw + tg];
                af[mt][1] = Asw[(r + 8) * WSTRIDE + kw + tg];
                af[mt][2] = Asw[r * WSTRIDE + kw + 4 + tg];
                af[mt][3] = Asw[(r + 8) * WSTRIDE + kw + 4 + tg];
            }
#pragma unroll
            for (int nt = 0; nt < 4; nt++) {
                int r = wn + nt * 8 + g;
                bf[nt][0] = Wsw[r * WSTRIDE + kw + tg];
                bf[nt][1] = Wsw[r * WSTRIDE + kw + 4 + tg];
            }
#pragma unroll
            for (int mt = 0; mt < 4; mt++)
#pragma unroll
                for (int nt = 0; nt < 4; nt++) {
                    asm volatile(
                        "mma.sync.aligned.m16n8k16.row.col.f32.f16.f16.f32 "
                        "{%0,%1,%2,%3}, {%4,%5,%6,%7}, {%8,%9}, {%0,%1,%2,%3};"
                        : "+f"(acc[mt][nt][0]), "+f"(acc[mt][nt][1]),
                          "+f"(acc[mt][nt][2]), "+f"(acc[mt][nt][3])
                        : "r"(af[mt][0]), "r"(af[mt][1]),
                          "r"(af[mt][2]), "r"(af[mt][3]),
                          "r"(bf[nt][0]), "r"(bf[nt][1]));
                }
        }
    }

#pragma unroll
    for (int mt = 0; mt < 4; mt++) {
        int row0 = bm + wm + mt * 16 + g;
#pragma unroll
        for (int nt = 0; nt < 4; nt++) {
            int col = bn + wn + nt * 8 + tg * 2;
            float b0v = bias[col], b1v = bias[col + 1];
            if (sel == 2) {
                if (row0 < M) {
                    __half2 h = __floats2half2_rn(acc[mt][nt][0] + b0v,
                                                  acc[mt][nt][1] + b1v);
                    *(__half2*)(g_vh + (size_t)row0 * D + col) = h;
                }
                if (row0 + 8 < M) {
                    __half2 h = __floats2half2_rn(acc[mt][nt][2] + b0v,
                                                  acc[mt][nt][3] + b1v);
                    *(__half2*)(g_vh + (size_t)(row0 + 8) * D + col) = h;
                }
            } else {
                if (row0 < M) {
                    float2 o;
                    o.x = (acc[mt][nt][0] + b0v) * scale;
                    o.y = (acc[mt][nt][1] + b1v) * scale;
                    *(float2*)(C + (size_t)row0 * D + col) = o;
                }
                if (row0 + 8 < M) {
                    float2 o;
                    o.x = (acc[mt][nt][2] + b0v) * scale;
                    o.y = (acc[mt][nt][3] + b1v) * scale;
                    *(float2*)(C + (size_t)(row0 + 8) * D + col) = o;
                }
            }
        }
    }
}

// ---------------- CSR build (by dst) ----------------
__global__ void zero_cnt_kernel(int n) {
    int i = blockIdx.x * blockDim.x + threadIdx.x;
    if (i < n) g_cnt[i] = 0;
}
__global__ void hist_kernel(const int* __restrict__ dst, int E) {
    int i = blockIdx.x * blockDim.x + threadIdx.x;
    if (i < E) atomicAdd(&g_cnt[dst[i]], 1);
}
__global__ void scan_kernel(int n) {
    __shared__ int sdata[1024];
    __shared__ int carry_s;
    int t = threadIdx.x;
    if (t == 0) carry_s = 0;
    __syncthreads();
    for (int base = 0; base < n; base += 1024) {
        int idx = base + t;
        int v = (idx < n) ? g_cnt[idx] : 0;
        sdata[t] = v;
        __syncthreads();
        for (int off = 1; off < 1024; off <<= 1) {
            int tmp = (t >= off) ? sdata[t - off] : 0;
            __syncthreads();
            sdata[t] += tmp;
            __syncthreads();
        }
        int incl = sdata[t];
        int carry = carry_s;
        if (idx < n) {
            int excl = carry + incl - v;
            g_off[idx] = excl;
            g_cur[idx] = excl;
        }
        __syncthreads();
        if (t == 1023) carry_s = carry + incl;
        __syncthreads();
    }
    if (t == 0) g_off[n] = carry_s;
}
__global__ void scatter_kernel(const int* __restrict__ src,
                               const int* __restrict__ dst, int E) {
    int i = blockIdx.x * blockDim.x + threadIdx.x;
    if (i < E) {
        int p = atomicAdd(&g_cur[dst[i]], 1);
        g_srcs[p] = src[i];
    }
}

// ---------------- warp-per-dst attention (no smem, no block barriers) ------
__global__ __launch_bounds__(256)
void attn_kernel(int n) {
    const unsigned FULL = 0xffffffffu;
    int lane = threadIdx.x & 31;
    int dnode = blockIdx.x * 8 + (threadIdx.x >> 5);
    if (dnode >= n) return;
    int beg = g_off[dnode], deg = g_off[dnode + 1] - beg;

    const float4* qr = (const float4*)(g_q + (size_t)dnode * D);
    float4 q4[4];
#pragma unroll
    for (int i = 0; i < 4; i++) q4[i] = qr[lane + 32 * i];

    // pass 1: whole-warp dot per edge; score owned by lane idx&31
    float sc[4];
    float wmax = -3.4e38f;
    for (int idx = 0; idx < deg; idx++) {
        int s = g_srcs[beg + idx];
        const float4* kr = (const float4*)(g_k + (size_t)s * D);
        float acc = 0.f;
#pragma unroll
        for (int i = 0; i < 4; i++) {
            float4 kv = kr[lane + 32 * i];
            acc += kv.x * q4[i].x + kv.y * q4[i].y
                 + kv.z * q4[i].z + kv.w * q4[i].w;
        }
#pragma unroll
        for (int o = 16; o > 0; o >>= 1)
            acc += __shfl_down_sync(FULL, acc, o);
        acc = __shfl_sync(FULL, acc, 0);
        if ((idx & 31) == lane) sc[idx >> 5] = acc;
        wmax = fmaxf(wmax, acc);
    }

    // pass 2: exp + denom
    float ex[4];
    float ds = 0.f;
#pragma unroll
    for (int slot = 0; slot < 4; slot++) {
        int idx = slot * 32 + lane;
        if (idx < deg) { ex[slot] = expf(sc[slot] - wmax); ds += ex[slot]; }
        else ex[slot] = 0.f;
    }
#pragma unroll
    for (int o = 16; o > 0; o >>= 1)
        ds += __shfl_down_sync(FULL, ds, o);
    ds = __shfl_sync(FULL, ds, 0);
    float inv = 1.f / ds;

    // pass 3: accumulate fp16 v rows; lane owns halves [8l..8l+7],[256+8l..]
    float a[16];
#pragma unroll
    for (int i = 0; i < 16; i++) a[i] = 0.f;
    for (int idx = 0; idx < deg; idx++) {
        float al = __shfl_sync(FULL, ex[idx >> 5], idx & 31) * inv;
        int s = g_srcs[beg + idx];
        const uint4* vr = (const uint4*)(g_vh + (size_t)s * D);
        uint4 r0 = vr[lane];
        uint4 r1 = vr[lane + 32];
        const __half2* h0 = (const __half2*)&r0;
        const __half2* h1 = (const __half2*)&r1;
#pragma unroll
        for (int j = 0; j < 4; j++) {
            float2 f0 = __half22float2(h0[j]);
            float2 f1 = __half22float2(h1[j]);
            a[2 * j + 0] += al * f0.x;
            a[2 * j + 1] += al * f0.y;
            a[8 + 2 * j + 0] += al * f1.x;
            a[8 + 2 * j + 1] += al * f1.y;
        }
    }

    // writeback as fp16 (O-GEMM input)
    __half* arow = g_ah + (size_t)dnode * D;
    uint4 u0, u1;
    u0.x = h2bits(__floats2half2_rn(a[0], a[1]));
    u0.y = h2bits(__floats2half2_rn(a[2], a[3]));
    u0.z = h2bits(__floats2half2_rn(a[4], a[5]));
    u0.w = h2bits(__floats2half2_rn(a[6], a[7]));
    u1.x = h2bits(__floats2half2_rn(a[8], a[9]));
    u1.y = h2bits(__floats2half2_rn(a[10], a[11]));
    u1.z = h2bits(__floats2half2_rn(a[12], a[13]));
    u1.w = h2bits(__floats2half2_rn(a[14], a[15]));
    ((uint4*)arow)[lane] = u0;
    ((uint4*)(arow + 256))[lane] = u1;
}

// ---------------- launch ----------------
extern "C" void kernel_launch(void* const* d_in, const int* in_sizes, int n_in,
                              void* d_out, int out_size) {
    const float* x  = (const float*)d_in[0];
    const int*   src = (const int*)d_in[1];
    const int*   dst = (const int*)d_in[2];
    const float* Wq = (const float*)d_in[3];
    const float* bq = (const float*)d_in[4];
    const float* Wk = (const float*)d_in[5];
    const float* bk = (const float*)d_in[6];
    const float* Wv = (const float*)d_in[7];
    const float* bv = (const float*)d_in[8];
    const float* Wo = (const float*)d_in[9];
    const float* bo = (const float*)d_in[10];
    float* out = (float*)d_out;

    int n = in_sizes[0] / D;
    int E = in_sizes[1];
    float qscale = 1.f / sqrtf((float)D);

    static cudaStream_t s2 = nullptr;
    static cudaEvent_t evFork = nullptr, evW = nullptr, evJoin = nullptr;
    if (!s2) {
        cudaStreamCreateWithFlags(&s2, cudaStreamNonBlocking);
        cudaEventCreateWithFlags(&evFork, cudaEventDisableTiming);
        cudaEventCreateWithFlags(&evW, cudaEventDisableTiming);
        cudaEventCreateWithFlags(&evJoin, cudaEventDisableTiming);
    }

    cudaFuncSetAttribute(tgemm_kernel,
                         cudaFuncAttributeMaxDynamicSharedMemorySize, GEMM_SMEM);

    cudaEventRecord(evFork, 0);
    cudaStreamWaitEvent(s2, evFork, 0);

    convw_kernel<<<(4 * D * D / 4 + 255) / 256, 256, 0, s2>>>(Wq, Wk, Wv, Wo);
    cudaEventRecord(evW, s2);
    zero_cnt_kernel<<<(n + 255) / 256, 256, 0, s2>>>(n);
    hist_kernel<<<(E + 255) / 256, 256, 0, s2>>>(dst, E);
    scan_kernel<<<1, 1024, 0, s2>>>(n);
    scatter_kernel<<<(E + 255) / 256, 256, 0, s2>>>(src, dst, E);
    cudaEventRecord(evJoin, s2);

    logmap_kernel<<<n, 128>>>(x, n);
    cudaStreamWaitEvent(0, evW, 0);

    dim3 gqkv(12, (n + 127) / 128);
    tgemm_kernel<<<gqkv, 256, GEMM_SMEM>>>(bq, bk, bv, 0, n, qscale);

    cudaStreamWaitEvent(0, evJoin, 0);
    attn_kernel<<<(n + 7) / 8, 256>>>(n);

    dim3 go(4, (n + 127) / 128);
    tgemm_kernel<<<go, 256, GEMM_SMEM>>>(bo, bo, bo, 1, n, 1.f);
    expmap_kernel<<<n, 128>>>(out, n);
}

// round 15
// speedup vs baseline: 1.5317x; 1.0236x over previous
#include <cuda_runtime.h>
#include <cuda_fp16.h>
#include <math.h>
#include <stdint.h>

#define D 512
#define NMAX 20000
#define EMAX 320000

// ---------------- scratch (device globals: allocation-free) ----------------
__device__ __half g_th[NMAX * D];    // tangent vectors, fp16
__device__ float  g_q[NMAX * D];     // q (fp32; attention reads it)
__device__ float  g_k[NMAX * D];     // k (fp32; attention reads it)
__device__ __half g_vh[NMAX * D];    // v (fp16; attention pass 3)
__device__ __half g_ah[NMAX * D];    // attn output, fp16 (O-GEMM input)
__device__ __half g_Wh[4 * D * D];   // fp16 weight copies (q,k,v,o)
__device__ float  g_scores[EMAX];
__device__ int    g_cnt[NMAX];
__device__ int    g_off[NMAX + 1];
__device__ int    g_cur[NMAX];
__device__ int    g_srcs[EMAX];      // src node id in CSR order

__device__ __forceinline__ void cp_async16(void* sptr, const void* gptr, bool pred) {
    uint32_t sa = (uint32_t)__cvta_generic_to_shared(sptr);
    int sz = pred ? 16 : 0;
    asm volatile("cp.async.cg.shared.global [%0], [%1], 16, %2;\n"
                 :: "r"(sa), "l"(gptr), "r"(sz));
}

__device__ __forceinline__ uint32_t h2bits(__half2 h) {
    return *reinterpret_cast<uint32_t*>(&h);
}

// ---------------- W conversion (fp16 round, once per call) -----------------
__global__ void convw_kernel(const float* __restrict__ Wq, const float* __restrict__ Wk,
                             const float* __restrict__ Wv, const float* __restrict__ Wo) {
    int i = blockIdx.x * blockDim.x + threadIdx.x;   // float4 index
    int total = 4 * D * D / 4;
    if (i >= total) return;
    int which = i / (D * D / 4);
    int off = i - which * (D * D / 4);
    const float* src = (which == 0) ? Wq : (which == 1) ? Wk : (which == 2) ? Wv : Wo;
    float4 v = ((const float4*)src)[off];
    uint2 o;
    o.x = h2bits(__floats2half2_rn(v.x, v.y));
    o.y = h2bits(__floats2half2_rn(v.z, v.w));
    ((uint2*)(g_Wh + (size_t)which * D * D))[off] = o;
}

// ---------------- logmap0 (writes fp16 tangent) ----------------------------
__global__ void logmap_kernel(const float* __restrict__ x, int n) {
    int row = blockIdx.x;
    if (row >= n) return;
    const float4* xr = (const float4*)(x + (size_t)row * D);
    float4 xv = xr[threadIdx.x];
    float ss = xv.x * xv.x + xv.y * xv.y + xv.z * xv.z + xv.w * xv.w;
    for (int o = 16; o > 0; o >>= 1) ss += __shfl_down_sync(0xffffffffu, ss, o);
    __shared__ float sred[4];
    int lane = threadIdx.x & 31, w = threadIdx.x >> 5;
    if (lane == 0) sred[w] = ss;
    __syncthreads();
    float tot = sred[0] + sred[1] + sred[2] + sred[3];
    float nrm = sqrtf(tot);
    float nc = fminf(fmaxf(nrm, 1e-7f), 1.f - 1e-6f);
    float fac = atanhf(nc) / nc;
    uint2 o;
    o.x = h2bits(__floats2half2_rn(fac * xv.x, fac * xv.y));
    o.y = h2bits(__floats2half2_rn(fac * xv.z, fac * xv.w));
    ((uint2*)(g_th + (size_t)row * D))[threadIdx.x] = o;
}

// ---------------- expmap0 (reads g_q as h, writes output) ------------------
__global__ void expmap_kernel(float* __restrict__ out, int n) {
    int row = blockIdx.x;
    if (row >= n) return;
    const float4* hr = (const float4*)(g_q + (size_t)row * D);
    float4 hv = hr[threadIdx.x];
    float ss = hv.x * hv.x + hv.y * hv.y + hv.z * hv.z + hv.w * hv.w;
    for (int o = 16; o > 0; o >>= 1) ss += __shfl_down_sync(0xffffffffu, ss, o);
    __shared__ float sred[4];
    int lane = threadIdx.x & 31, w = threadIdx.x >> 5;
    if (lane == 0) sred[w] = ss;
    __syncthreads();
    float tot = sred[0] + sred[1] + sred[2] + sred[3];
    float nrm = sqrtf(tot);
    float nc = fmaxf(nrm, 1e-7f);
    float fac = tanhf(nc) / nc;
    float4 o4;
    o4.x = fac * hv.x; o4.y = fac * hv.y; o4.z = fac * hv.z; o4.w = fac * hv.w;
    ((float4*)(out + (size_t)row * D))[threadIdx.x] = o4;
}

// ---------------- FP16 tensor-core GEMM (3-stage, m16n8k16, ldmatrix) ------
//   C[M,512] = (A[M,512] @ W[512,512]^T + bias) * scale ; fp32 accumulate
// mode 0 (QKV): grid.x = 12, sel = bx>>2 (0/1/2), bn = (bx&3)*128, A = g_th
//   sel==2 (V) writes g_vh as __half2.
// mode 1 (O):   grid.x = 4,  sel = 3, bn = bx*128, A = g_ah, C = g_q
// HSTRIDE 40 halves (80 B rows): ldmatrix 8-row fetch hits word-bank quads
// {20r..20r+3} mod 32, all disjoint -> conflict-free.
#define HSTRIDE 40
#define TILE_HALFS (128 * HSTRIDE)
#define NSTAGE 3
#define GEMM_SMEM (NSTAGE * 2 * TILE_HALFS * 2)   // 61440 bytes

__global__ __launch_bounds__(256, 2)
void tgemm_kernel(const float* __restrict__ b0, const float* __restrict__ b1,
                  const float* __restrict__ b2, int mode, int M, float qscale) {
    extern __shared__ __half smem_h[];
    int sel, bn;
    if (mode == 0) { sel = blockIdx.x >> 2; bn = (blockIdx.x & 3) << 7; }
    else           { sel = 3;               bn = blockIdx.x << 7; }
    const __half* __restrict__ A = (sel == 3) ? g_ah : g_th;
    const __half* __restrict__ W = g_Wh + (size_t)sel * D * D;
    float* __restrict__ C = (sel == 1) ? g_k : g_q;   // sel 2 uses g_vh path
    const float* __restrict__ bias = (sel == 1) ? b1 : (sel == 2) ? b2 : b0;
    float scale = (sel == 0) ? qscale : 1.f;

    int bm = blockIdx.y * 128;
    int tid = threadIdx.x;
    int lane = tid & 31, warp = tid >> 5;
    int wm = (warp >> 2) * 64;
    int wn = (warp & 3) * 32;
    int g = lane >> 2, tg = lane & 3;

    uint32_t smem_base = (uint32_t)__cvta_generic_to_shared(smem_h);

    float acc[4][4][4];
#pragma unroll
    for (int mt = 0; mt < 4; mt++)
#pragma unroll
        for (int nt = 0; nt < 4; nt++)
#pragma unroll
            for (int i = 0; i < 4; i++) acc[mt][nt][i] = 0.f;

    auto prefetch = [&](int it) {
        __half* As = smem_h + (it % NSTAGE) * 2 * TILE_HALFS;
        __half* Ws = As + TILE_HALFS;
        int k0 = it * 32;
#pragma unroll
        for (int i = 0; i < 2; i++) {
            int ci = tid + i * 256;           // 512 chunks of 16B per matrix
            int row = ci >> 2, col8 = (ci & 3) * 8;
            int ga = bm + row;
            cp_async16(&As[row * HSTRIDE + col8],
                       A + (size_t)ga * D + k0 + col8, ga < M);
            cp_async16(&Ws[row * HSTRIDE + col8],
                       W + (size_t)(bn + row) * D + k0 + col8, true);
        }
        asm volatile("cp.async.commit_group;\n" ::);
    };

    prefetch(0);
    prefetch(1);

    // ldmatrix per-lane row/khalf assignment (constant across iterations)
    int a_row_off = (lane & 7) + ((lane >> 3) & 1) * 8;  // row within m16 tile
    int a_k_off = (lane >> 4) * 8;                       // klo / khi
    int b_row_off = lane & 7;                            // row within n8 tile
    int b_k_off = ((lane >> 3) & 1) * 8;                 // klo / khi (lanes 0-15)

    for (int it = 0; it < 16; it++) {
        if (it < 15) {
            asm volatile("cp.async.wait_group 1;\n" ::);
        } else {
            asm volatile("cp.async.wait_group 0;\n" ::);
        }
        __syncthreads();
        if (it + 2 < 16) prefetch(it + 2);

        uint32_t a_base = smem_base + (uint32_t)((it % NSTAGE) * 2 * TILE_HALFS) * 2;
        uint32_t w_base = a_base + (uint32_t)TILE_HALFS * 2;

#pragma unroll
        for (int ks = 0; ks < 2; ks++) {
            int kh = ks * 16;                 // half-index base of this k16
            uint32_t af[4][4], bf[4][2];
#pragma unroll
            for (int mt = 0; mt < 4; mt++) {
                int r = wm + mt * 16 + a_row_off;
                uint32_t addr = a_base + (uint32_t)(r * HSTRIDE + kh + a_k_off) * 2;
                asm volatile(
                    "ldmatrix.sync.aligned.m8n8.x4.shared.b16 {%0,%1,%2,%3}, [%4];"
                    : "=r"(af[mt][0]), "=r"(af[mt][1]),
                      "=r"(af[mt][2]), "=r"(af[mt][3])
                    : "r"(addr));
            }
#pragma unroll
            for (int nt = 0; nt < 4; nt++) {
                int r = wn + nt * 8 + b_row_off;
                uint32_t addr = w_base + (uint32_t)(r * HSTRIDE + kh + b_k_off) * 2;
                asm volatile(
                    "ldmatrix.sync.aligned.m8n8.x2.shared.b16 {%0,%1}, [%2];"
                    : "=r"(bf[nt][0]), "=r"(bf[nt][1])
                    : "r"(addr));
            }
#pragma unroll
            for (int mt = 0; mt < 4; mt++)
#pragma unroll
                for (int nt = 0; nt < 4; nt++) {
                    asm volatile(
                        "mma.sync.aligned.m16n8k16.row.col.f32.f16.f16.f32 "
                        "{%0,%1,%2,%3}, {%4,%5,%6,%7}, {%8,%9}, {%0,%1,%2,%3};"
                        : "+f"(acc[mt][nt][0]), "+f"(acc[mt][nt][1]),
                          "+f"(acc[mt][nt][2]), "+f"(acc[mt][nt][3])
                        : "r"(af[mt][0]), "r"(af[mt][1]),
                          "r"(af[mt][2]), "r"(af[mt][3]),
                          "r"(bf[nt][0]), "r"(bf[nt][1]));
                }
        }
    }

#pragma unroll
    for (int mt = 0; mt < 4; mt++) {
        int row0 = bm + wm + mt * 16 + g;
#pragma unroll
        for (int nt = 0; nt < 4; nt++) {
            int col = bn + wn + nt * 8 + tg * 2;
            float b0v = bias[col], b1v = bias[col + 1];
            if (sel == 2) {
                if (row0 < M) {
                    __half2 h = __floats2half2_rn(acc[mt][nt][0] + b0v,
                                                  acc[mt][nt][1] + b1v);
                    *(__half2*)(g_vh + (size_t)row0 * D + col) = h;
                }
                if (row0 + 8 < M) {
                    __half2 h = __floats2half2_rn(acc[mt][nt][2] + b0v,
                                                  acc[mt][nt][3] + b1v);
                    *(__half2*)(g_vh + (size_t)(row0 + 8) * D + col) = h;
                }
            } else {
                if (row0 < M) {
                    float2 o;
                    o.x = (acc[mt][nt][0] + b0v) * scale;
                    o.y = (acc[mt][nt][1] + b1v) * scale;
                    *(float2*)(C + (size_t)row0 * D + col) = o;
                }
                if (row0 + 8 < M) {
                    float2 o;
                    o.x = (acc[mt][nt][2] + b0v) * scale;
                    o.y = (acc[mt][nt][3] + b1v) * scale;
                    *(float2*)(C + (size_t)(row0 + 8) * D + col) = o;
                }
            }
        }
    }
}

// ---------------- CSR build (by dst) ----------------
__global__ void zero_cnt_kernel(int n) {
    int i = blockIdx.x * blockDim.x + threadIdx.x;
    if (i < n) g_cnt[i] = 0;
}
__global__ void hist_kernel(const int* __restrict__ dst, int E) {
    int i = blockIdx.x * blockDim.x + threadIdx.x;
    if (i < E) atomicAdd(&g_cnt[dst[i]], 1);
}
__global__ void scan_kernel(int n) {
    __shared__ int sdata[1024];
    __shared__ int carry_s;
    int t = threadIdx.x;
    if (t == 0) carry_s = 0;
    __syncthreads();
    for (int base = 0; base < n; base += 1024) {
        int idx = base + t;
        int v = (idx < n) ? g_cnt[idx] : 0;
        sdata[t] = v;
        __syncthreads();
        for (int off = 1; off < 1024; off <<= 1) {
            int tmp = (t >= off) ? sdata[t - off] : 0;
            __syncthreads();
            sdata[t] += tmp;
            __syncthreads();
        }
        int incl = sdata[t];
        int carry = carry_s;
        if (idx < n) {
            int excl = carry + incl - v;
            g_off[idx] = excl;
            g_cur[idx] = excl;
        }
        __syncthreads();
        if (t == 1023) carry_s = carry + incl;
        __syncthreads();
    }
    if (t == 0) g_off[n] = carry_s;
}
__global__ void scatter_kernel(const int* __restrict__ src,
                               const int* __restrict__ dst, int E) {
    int i = blockIdx.x * blockDim.x + threadIdx.x;
    if (i < E) {
        int p = atomicAdd(&g_cur[dst[i]], 1);
        g_srcs[p] = src[i];
    }
}

// ---------------- warp-per-dst attention (no smem, no block barriers) ------
__global__ __launch_bounds__(256)
void attn_kernel(int n) {
    const unsigned FULL = 0xffffffffu;
    int lane = threadIdx.x & 31;
    int dnode = blockIdx.x * 8 + (threadIdx.x >> 5);
    if (dnode >= n) return;
    int beg = g_off[dnode], deg = g_off[dnode + 1] - beg;

    const float4* qr = (const float4*)(g_q + (size_t)dnode * D);
    float4 q4[4];
#pragma unroll
    for (int i = 0; i < 4; i++) q4[i] = qr[lane + 32 * i];

    // pass 1: whole-warp dot per edge; score owned by lane idx&31
    float sc[4];
    float wmax = -3.4e38f;
    for (int idx = 0; idx < deg; idx++) {
        int s = g_srcs[beg + idx];
        const float4* kr = (const float4*)(g_k + (size_t)s * D);
        float acc = 0.f;
#pragma unroll
        for (int i = 0; i < 4; i++) {
            float4 kv = kr[lane + 32 * i];
            acc += kv.x * q4[i].x + kv.y * q4[i].y
                 + kv.z * q4[i].z + kv.w * q4[i].w;
        }
#pragma unroll
        for (int o = 16; o > 0; o >>= 1)
            acc += __shfl_down_sync(FULL, acc, o);
        acc = __shfl_sync(FULL, acc, 0);
        if ((idx & 31) == lane) sc[idx >> 5] = acc;
        wmax = fmaxf(wmax, acc);
    }

    // pass 2: exp + denom
    float ex[4];
    float ds = 0.f;
#pragma unroll
    for (int slot = 0; slot < 4; slot++) {
        int idx = slot * 32 + lane;
        if (idx < deg) { ex[slot] = expf(sc[slot] - wmax); ds += ex[slot]; }
        else ex[slot] = 0.f;
    }
#pragma unroll
    for (int o = 16; o > 0; o >>= 1)
        ds += __shfl_down_sync(FULL, ds, o);
    ds = __shfl_sync(FULL, ds, 0);
    float inv = 1.f / ds;

    // pass 3: accumulate fp16 v rows; lane owns halves [8l..8l+7],[256+8l..]
    float a[16];
#pragma unroll
    for (int i = 0; i < 16; i++) a[i] = 0.f;
    for (int idx = 0; idx < deg; idx++) {
        float al = __shfl_sync(FULL, ex[idx >> 5], idx & 31) * inv;
        int s = g_srcs[beg + idx];
        const uint4* vr = (const uint4*)(g_vh + (size_t)s * D);
        uint4 r0 = vr[lane];
        uint4 r1 = vr[lane + 32];
        const __half2* h0 = (const __half2*)&r0;
        const __half2* h1 = (const __half2*)&r1;
#pragma unroll
        for (int j = 0; j < 4; j++) {
            float2 f0 = __half22float2(h0[j]);
            float2 f1 = __half22float2(h1[j]);
            a[2 * j + 0] += al * f0.x;
            a[2 * j + 1] += al * f0.y;
            a[8 + 2 * j + 0] += al * f1.x;
            a[8 + 2 * j + 1] += al * f1.y;
        }
    }

    // writeback as fp16 (O-GEMM input)
    __half* arow = g_ah + (size_t)dnode * D;
    uint4 u0, u1;
    u0.x = h2bits(__floats2half2_rn(a[0], a[1]));
    u0.y = h2bits(__floats2half2_rn(a[2], a[3]));
    u0.z = h2bits(__floats2half2_rn(a[4], a[5]));
    u0.w = h2bits(__floats2half2_rn(a[6], a[7]));
    u1.x = h2bits(__floats2half2_rn(a[8], a[9]));
    u1.y = h2bits(__floats2half2_rn(a[10], a[11]));
    u1.z = h2bits(__floats2half2_rn(a[12], a[13]));
    u1.w = h2bits(__floats2half2_rn(a[14], a[15]));
    ((uint4*)arow)[lane] = u0;
    ((uint4*)(arow + 256))[lane] = u1;
}

// ---------------- launch ----------------
extern "C" void kernel_launch(void* const* d_in, const int* in_sizes, int n_in,
                              void* d_out, int out_size) {
    const float* x  = (const float*)d_in[0];
    const int*   src = (const int*)d_in[1];
    const int*   dst = (const int*)d_in[2];
    const float* Wq = (const float*)d_in[3];
    const float* bq = (const float*)d_in[4];
    const float* Wk = (const float*)d_in[5];
    const float* bk = (const float*)d_in[6];
    const float* Wv = (const float*)d_in[7];
    const float* bv = (const float*)d_in[8];
    const float* Wo = (const float*)d_in[9];
    const float* bo = (const float*)d_in[10];
    float* out = (float*)d_out;

    int n = in_sizes[0] / D;
    int E = in_sizes[1];
    float qscale = 1.f / sqrtf((float)D);

    static cudaStream_t s2 = nullptr;
    static cudaEvent_t evFork = nullptr, evW = nullptr, evJoin = nullptr;
    if (!s2) {
        cudaStreamCreateWithFlags(&s2, cudaStreamNonBlocking);
        cudaEventCreateWithFlags(&evFork, cudaEventDisableTiming);
        cudaEventCreateWithFlags(&evW, cudaEventDisableTiming);
        cudaEventCreateWithFlags(&evJoin, cudaEventDisableTiming);
    }

    cudaFuncSetAttribute(tgemm_kernel,
                         cudaFuncAttributeMaxDynamicSharedMemorySize, GEMM_SMEM);

    cudaEventRecord(evFork, 0);
    cudaStreamWaitEvent(s2, evFork, 0);

    convw_kernel<<<(4 * D * D / 4 + 255) / 256, 256, 0, s2>>>(Wq, Wk, Wv, Wo);
    cudaEventRecord(evW, s2);
    zero_cnt_kernel<<<(n + 255) / 256, 256, 0, s2>>>(n);
    hist_kernel<<<(E + 255) / 256, 256, 0, s2>>>(dst, E);
    scan_kernel<<<1, 1024, 0, s2>>>(n);
    scatter_kernel<<<(E + 255) / 256, 256, 0, s2>>>(src, dst, E);
    cudaEventRecord(evJoin, s2);

    logmap_kernel<<<n, 128>>>(x, n);
    cudaStreamWaitEvent(0, evW, 0);

    dim3 gqkv(12, (n + 127) / 128);
    tgemm_kernel<<<gqkv, 256, GEMM_SMEM>>>(bq, bk, bv, 0, n, qscale);

    cudaStreamWaitEvent(0, evJoin, 0);
    attn_kernel<<<(n + 7) / 8, 256>>>(n);

    dim3 go(4, (n + 127) / 128);
    tgemm_kernel<<<go, 256, GEMM_SMEM>>>(bo, bo, bo, 1, n, 1.f);
    expmap_kernel<<<n, 128>>>(out, n);
}

// round 16
// speedup vs baseline: 1.6477x; 1.0757x over previous
#include <cuda_runtime.h>
#include <cuda_fp16.h>
#include <math.h>
#include <stdint.h>

#define D 512
#define NMAX 20000
#define EMAX 320000

// ---------------- scratch (device globals: allocation-free) ----------------
__device__ __half g_th[NMAX * D];    // tangent vectors, fp16
__device__ float  g_q[NMAX * D];     // q (fp32) ; later reused as h
__device__ __half g_kh[NMAX * D];    // k (fp16; attention pass 1)
__device__ __half g_vh[NMAX * D];    // v (fp16; attention pass 3)
__device__ __half g_ah[NMAX * D];    // attn output, fp16 (O-GEMM input)
__device__ __half g_Wh[4 * D * D];   // fp16 weight copies (q,k,v,o)
__device__ float  g_scores[EMAX];
__device__ int    g_cnt[NMAX];
__device__ int    g_off[NMAX + 1];
__device__ int    g_cur[NMAX];
__device__ int    g_srcs[EMAX];      // src node id in CSR order

__device__ __forceinline__ void cp_async16(void* sptr, const void* gptr, bool pred) {
    uint32_t sa = (uint32_t)__cvta_generic_to_shared(sptr);
    int sz = pred ? 16 : 0;
    asm volatile("cp.async.cg.shared.global [%0], [%1], 16, %2;\n"
                 :: "r"(sa), "l"(gptr), "r"(sz));
}

__device__ __forceinline__ uint32_t h2bits(__half2 h) {
    return *reinterpret_cast<uint32_t*>(&h);
}

// ---------------- W conversion (fp16 round, once per call) -----------------
__global__ void convw_kernel(const float* __restrict__ Wq, const float* __restrict__ Wk,
                             const float* __restrict__ Wv, const float* __restrict__ Wo) {
    int i = blockIdx.x * blockDim.x + threadIdx.x;   // float4 index
    int total = 4 * D * D / 4;
    if (i >= total) return;
    int which = i / (D * D / 4);
    int off = i - which * (D * D / 4);
    const float* src = (which == 0) ? Wq : (which == 1) ? Wk : (which == 2) ? Wv : Wo;
    float4 v = ((const float4*)src)[off];
    uint2 o;
    o.x = h2bits(__floats2half2_rn(v.x, v.y));
    o.y = h2bits(__floats2half2_rn(v.z, v.w));
    ((uint2*)(g_Wh + (size_t)which * D * D))[off] = o;
}

// ---------------- logmap0 (writes fp16 tangent) ----------------------------
__global__ void logmap_kernel(const float* __restrict__ x, int n) {
    int row = blockIdx.x;
    if (row >= n) return;
    const float4* xr = (const float4*)(x + (size_t)row * D);
    float4 xv = xr[threadIdx.x];
    float ss = xv.x * xv.x + xv.y * xv.y + xv.z * xv.z + xv.w * xv.w;
    for (int o = 16; o > 0; o >>= 1) ss += __shfl_down_sync(0xffffffffu, ss, o);
    __shared__ float sred[4];
    int lane = threadIdx.x & 31, w = threadIdx.x >> 5;
    if (lane == 0) sred[w] = ss;
    __syncthreads();
    float tot = sred[0] + sred[1] + sred[2] + sred[3];
    float nrm = sqrtf(tot);
    float nc = fminf(fmaxf(nrm, 1e-7f), 1.f - 1e-6f);
    float fac = atanhf(nc) / nc;
    uint2 o;
    o.x = h2bits(__floats2half2_rn(fac * xv.x, fac * xv.y));
    o.y = h2bits(__floats2half2_rn(fac * xv.z, fac * xv.w));
    ((uint2*)(g_th + (size_t)row * D))[threadIdx.x] = o;
}

// ---------------- expmap0 (reads g_q as h, writes output) ------------------
__global__ void expmap_kernel(float* __restrict__ out, int n) {
    int row = blockIdx.x;
    if (row >= n) return;
    const float4* hr = (const float4*)(g_q + (size_t)row * D);
    float4 hv = hr[threadIdx.x];
    float ss = hv.x * hv.x + hv.y * hv.y + hv.z * hv.z + hv.w * hv.w;
    for (int o = 16; o > 0; o >>= 1) ss += __shfl_down_sync(0xffffffffu, ss, o);
    __shared__ float sred[4];
    int lane = threadIdx.x & 31, w = threadIdx.x >> 5;
    if (lane == 0) sred[w] = ss;
    __syncthreads();
    float tot = sred[0] + sred[1] + sred[2] + sred[3];
    float nrm = sqrtf(tot);
    float nc = fmaxf(nrm, 1e-7f);
    float fac = tanhf(nc) / nc;
    float4 o4;
    o4.x = fac * hv.x; o4.y = fac * hv.y; o4.z = fac * hv.z; o4.w = fac * hv.w;
    ((float4*)(out + (size_t)row * D))[threadIdx.x] = o4;
}

// ---------------- FP16 tensor-core GEMM (4-stage, m16n8k16, ldmatrix) ------
//   C[M,512] = (A[M,512] @ W[512,512]^T + bias) * scale ; fp32 accumulate
// mode 0 (QKV): grid.x = 12, sel = bx>>2 (0/1/2), bn = (bx&3)*128, A = g_th
//   sel==1 (K) writes g_kh, sel==2 (V) writes g_vh as __half2.
// mode 1 (O):   grid.x = 4,  sel = 3, bn = bx*128, A = g_ah, C = g_q
#define HSTRIDE 40
#define TILE_HALFS (128 * HSTRIDE)
#define NSTAGE 4
#define GEMM_SMEM (NSTAGE * 2 * TILE_HALFS * 2)   // 81920 bytes

__global__ __launch_bounds__(256, 2)
void tgemm_kernel(const float* __restrict__ b0, const float* __restrict__ b1,
                  const float* __restrict__ b2, int mode, int M, float qscale) {
    extern __shared__ __half smem_h[];
    int sel, bn;
    if (mode == 0) { sel = blockIdx.x >> 2; bn = (blockIdx.x & 3) << 7; }
    else           { sel = 3;               bn = blockIdx.x << 7; }
    const __half* __restrict__ A = (sel == 3) ? g_ah : g_th;
    const __half* __restrict__ W = g_Wh + (size_t)sel * D * D;
    const float* __restrict__ bias = (sel == 1) ? b1 : (sel == 2) ? b2 : b0;
    float scale = (sel == 0) ? qscale : 1.f;

    int bm = blockIdx.y * 128;
    int tid = threadIdx.x;
    int lane = tid & 31, warp = tid >> 5;
    int wm = (warp >> 2) * 64;
    int wn = (warp & 3) * 32;
    int g = lane >> 2, tg = lane & 3;

    uint32_t smem_base = (uint32_t)__cvta_generic_to_shared(smem_h);

    float acc[4][4][4];
#pragma unroll
    for (int mt = 0; mt < 4; mt++)
#pragma unroll
        for (int nt = 0; nt < 4; nt++)
#pragma unroll
            for (int i = 0; i < 4; i++) acc[mt][nt][i] = 0.f;

    auto prefetch = [&](int it) {
        __half* As = smem_h + (it % NSTAGE) * 2 * TILE_HALFS;
        __half* Ws = As + TILE_HALFS;
        int k0 = it * 32;
#pragma unroll
        for (int i = 0; i < 2; i++) {
            int ci = tid + i * 256;
            int row = ci >> 2, col8 = (ci & 3) * 8;
            int ga = bm + row;
            cp_async16(&As[row * HSTRIDE + col8],
                       A + (size_t)ga * D + k0 + col8, ga < M);
            cp_async16(&Ws[row * HSTRIDE + col8],
                       W + (size_t)(bn + row) * D + k0 + col8, true);
        }
        asm volatile("cp.async.commit_group;\n" ::);
    };

    prefetch(0);
    prefetch(1);
    prefetch(2);

    int a_row_off = (lane & 7) + ((lane >> 3) & 1) * 8;
    int a_k_off = (lane >> 4) * 8;
    int b_row_off = lane & 7;
    int b_k_off = ((lane >> 3) & 1) * 8;

    for (int it = 0; it < 16; it++) {
        // In flight: {it, it+1, it+2}; wait 2 pending == tile `it` landed.
        if (it < 14) {
            asm volatile("cp.async.wait_group 2;\n" ::);
        } else if (it < 15) {
            asm volatile("cp.async.wait_group 1;\n" ::);
        } else {
            asm volatile("cp.async.wait_group 0;\n" ::);
        }
        __syncthreads();   // all warps done with compute(it-1)
        // prefetch(it+3) targets buf (it+3)%4 == (it-1)%4, fenced above.
        if (it + 3 < 16) prefetch(it + 3);

        uint32_t a_base = smem_base + (uint32_t)((it % NSTAGE) * 2 * TILE_HALFS) * 2;
        uint32_t w_base = a_base + (uint32_t)TILE_HALFS * 2;

#pragma unroll
        for (int ks = 0; ks < 2; ks++) {
            int kh = ks * 16;
            uint32_t af[4][4], bf[4][2];
#pragma unroll
            for (int mt = 0; mt < 4; mt++) {
                int r = wm + mt * 16 + a_row_off;
                uint32_t addr = a_base + (uint32_t)(r * HSTRIDE + kh + a_k_off) * 2;
                asm volatile(
                    "ldmatrix.sync.aligned.m8n8.x4.shared.b16 {%0,%1,%2,%3}, [%4];"
                    : "=r"(af[mt][0]), "=r"(af[mt][1]),
                      "=r"(af[mt][2]), "=r"(af[mt][3])
                    : "r"(addr));
            }
#pragma unroll
            for (int nt = 0; nt < 4; nt++) {
                int r = wn + nt * 8 + b_row_off;
                uint32_t addr = w_base + (uint32_t)(r * HSTRIDE + kh + b_k_off) * 2;
                asm volatile(
                    "ldmatrix.sync.aligned.m8n8.x2.shared.b16 {%0,%1}, [%2];"
                    : "=r"(bf[nt][0]), "=r"(bf[nt][1])
                    : "r"(addr));
            }
#pragma unroll
            for (int mt = 0; mt < 4; mt++)
#pragma unroll
                for (int nt = 0; nt < 4; nt++) {
                    asm volatile(
                        "mma.sync.aligned.m16n8k16.row.col.f32.f16.f16.f32 "
                        "{%0,%1,%2,%3}, {%4,%5,%6,%7}, {%8,%9}, {%0,%1,%2,%3};"
                        : "+f"(acc[mt][nt][0]), "+f"(acc[mt][nt][1]),
                          "+f"(acc[mt][nt][2]), "+f"(acc[mt][nt][3])
                        : "r"(af[mt][0]), "r"(af[mt][1]),
                          "r"(af[mt][2]), "r"(af[mt][3]),
                          "r"(bf[nt][0]), "r"(bf[nt][1]));
                }
        }
    }

#pragma unroll
    for (int mt = 0; mt < 4; mt++) {
        int row0 = bm + wm + mt * 16 + g;
#pragma unroll
        for (int nt = 0; nt < 4; nt++) {
            int col = bn + wn + nt * 8 + tg * 2;
            float b0v = bias[col], b1v = bias[col + 1];
            if (sel == 1 || sel == 2) {
                __half* dst16 = (sel == 1) ? g_kh : g_vh;
                if (row0 < M) {
                    __half2 h = __floats2half2_rn(acc[mt][nt][0] + b0v,
                                                  acc[mt][nt][1] + b1v);
                    *(__half2*)(dst16 + (size_t)row0 * D + col) = h;
                }
                if (row0 + 8 < M) {
                    __half2 h = __floats2half2_rn(acc[mt][nt][2] + b0v,
                                                  acc[mt][nt][3] + b1v);
                    *(__half2*)(dst16 + (size_t)(row0 + 8) * D + col) = h;
                }
            } else {
                if (row0 < M) {
                    float2 o;
                    o.x = (acc[mt][nt][0] + b0v) * scale;
                    o.y = (acc[mt][nt][1] + b1v) * scale;
                    *(float2*)(g_q + (size_t)row0 * D + col) = o;
                }
                if (row0 + 8 < M) {
                    float2 o;
                    o.x = (acc[mt][nt][2] + b0v) * scale;
                    o.y = (acc[mt][nt][3] + b1v) * scale;
                    *(float2*)(g_q + (size_t)(row0 + 8) * D + col) = o;
                }
            }
        }
    }
}

// ---------------- CSR build (by dst) ----------------
__global__ void zero_cnt_kernel(int n) {
    int i = blockIdx.x * blockDim.x + threadIdx.x;
    if (i < n) g_cnt[i] = 0;
}
__global__ void hist_kernel(const int* __restrict__ dst, int E) {
    int i = blockIdx.x * blockDim.x + threadIdx.x;
    if (i < E) atomicAdd(&g_cnt[dst[i]], 1);
}
__global__ void scan_kernel(int n) {
    __shared__ int sdata[1024];
    __shared__ int carry_s;
    int t = threadIdx.x;
    if (t == 0) carry_s = 0;
    __syncthreads();
    for (int base = 0; base < n; base += 1024) {
        int idx = base + t;
        int v = (idx < n) ? g_cnt[idx] : 0;
        sdata[t] = v;
        __syncthreads();
        for (int off = 1; off < 1024; off <<= 1) {
            int tmp = (t >= off) ? sdata[t - off] : 0;
            __syncthreads();
            sdata[t] += tmp;
            __syncthreads();
        }
        int incl = sdata[t];
        int carry = carry_s;
        if (idx < n) {
            int excl = carry + incl - v;
            g_off[idx] = excl;
            g_cur[idx] = excl;
        }
        __syncthreads();
        if (t == 1023) carry_s = carry + incl;
        __syncthreads();
    }
    if (t == 0) g_off[n] = carry_s;
}
__global__ void scatter_kernel(const int* __restrict__ src,
                               const int* __restrict__ dst, int E) {
    int i = blockIdx.x * blockDim.x + threadIdx.x;
    if (i < E) {
        int p = atomicAdd(&g_cur[dst[i]], 1);
        g_srcs[p] = src[i];
    }
}

// ---------------- warp-per-dst attention (k and v in fp16) -----------------
__global__ __launch_bounds__(256)
void attn_kernel(int n) {
    const unsigned FULL = 0xffffffffu;
    int lane = threadIdx.x & 31;
    int dnode = blockIdx.x * 8 + (threadIdx.x >> 5);
    if (dnode >= n) return;
    int beg = g_off[dnode], deg = g_off[dnode + 1] - beg;

    // q in registers, laid out to match fp16 k rows: lane owns floats
    // [8l..8l+7] and [256+8l..256+8l+7]
    const float4* qr = (const float4*)(g_q + (size_t)dnode * D);
    float4 q4[4];
    q4[0] = qr[lane * 2];
    q4[1] = qr[lane * 2 + 1];
    q4[2] = qr[64 + lane * 2];
    q4[3] = qr[64 + lane * 2 + 1];

    // pass 1: whole-warp dot per edge against fp16 k rows
    float sc[4];
    float wmax = -3.4e38f;
    for (int idx = 0; idx < deg; idx++) {
        int s = g_srcs[beg + idx];
        const uint4* kr = (const uint4*)(g_kh + (size_t)s * D);
        uint4 r0 = kr[lane];
        uint4 r1 = kr[lane + 32];
        const __half2* h0 = (const __half2*)&r0;
        const __half2* h1 = (const __half2*)&r1;
        float acc = 0.f;
#pragma unroll
        for (int j = 0; j < 2; j++) {
            float2 f0 = __half22float2(h0[2 * j]);
            float2 f1 = __half22float2(h0[2 * j + 1]);
            const float* qp = (const float*)&q4[j];
            acc += f0.x * qp[0] + f0.y * qp[1] + f1.x * qp[2] + f1.y * qp[3];
        }
#pragma unroll
        for (int j = 0; j < 2; j++) {
            float2 f0 = __half22float2(h1[2 * j]);
            float2 f1 = __half22float2(h1[2 * j + 1]);
            const float* qp = (const float*)&q4[2 + j];
            acc += f0.x * qp[0] + f0.y * qp[1] + f1.x * qp[2] + f1.y * qp[3];
        }
#pragma unroll
        for (int o = 16; o > 0; o >>= 1)
            acc += __shfl_down_sync(FULL, acc, o);
        acc = __shfl_sync(FULL, acc, 0);
        if ((idx & 31) == lane) sc[idx >> 5] = acc;
        wmax = fmaxf(wmax, acc);
    }

    // pass 2: exp + denom
    float ex[4];
    float ds = 0.f;
#pragma unroll
    for (int slot = 0; slot < 4; slot++) {
        int idx = slot * 32 + lane;
        if (idx < deg) { ex[slot] = expf(sc[slot] - wmax); ds += ex[slot]; }
        else ex[slot] = 0.f;
    }
#pragma unroll
    for (int o = 16; o > 0; o >>= 1)
        ds += __shfl_down_sync(FULL, ds, o);
    ds = __shfl_sync(FULL, ds, 0);
    float inv = 1.f / ds;

    // pass 3: accumulate fp16 v rows
    float a[16];
#pragma unroll
    for (int i = 0; i < 16; i++) a[i] = 0.f;
    for (int idx = 0; idx < deg; idx++) {
        float al = __shfl_sync(FULL, ex[idx >> 5], idx & 31) * inv;
        int s = g_srcs[beg + idx];
        const uint4* vr = (const uint4*)(g_vh + (size_t)s * D);
        uint4 r0 = vr[lane];
        uint4 r1 = vr[lane + 32];
        const __half2* h0 = (const __half2*)&r0;
        const __half2* h1 = (const __half2*)&r1;
#pragma unroll
        for (int j = 0; j < 4; j++) {
            float2 f0 = __half22float2(h0[j]);
            float2 f1 = __half22float2(h1[j]);
            a[2 * j + 0] += al * f0.x;
            a[2 * j + 1] += al * f0.y;
            a[8 + 2 * j + 0] += al * f1.x;
            a[8 + 2 * j + 1] += al * f1.y;
        }
    }

    // writeback as fp16 (O-GEMM input)
    __half* arow = g_ah + (size_t)dnode * D;
    uint4 u0, u1;
    u0.x = h2bits(__floats2half2_rn(a[0], a[1]));
    u0.y = h2bits(__floats2half2_rn(a[2], a[3]));
    u0.z = h2bits(__floats2half2_rn(a[4], a[5]));
    u0.w = h2bits(__floats2half2_rn(a[6], a[7]));
    u1.x = h2bits(__floats2half2_rn(a[8], a[9]));
    u1.y = h2bits(__floats2half2_rn(a[10], a[11]));
    u1.z = h2bits(__floats2half2_rn(a[12], a[13]));
    u1.w = h2bits(__floats2half2_rn(a[14], a[15]));
    ((uint4*)arow)[lane] = u0;
    ((uint4*)(arow + 256))[lane] = u1;
}

// ---------------- launch ----------------
extern "C" void kernel_launch(void* const* d_in, const int* in_sizes, int n_in,
                              void* d_out, int out_size) {
    const float* x  = (const float*)d_in[0];
    const int*   src = (const int*)d_in[1];
    const int*   dst = (const int*)d_in[2];
    const float* Wq = (const float*)d_in[3];
    const float* bq = (const float*)d_in[4];
    const float* Wk = (const float*)d_in[5];
    const float* bk = (const float*)d_in[6];
    const float* Wv = (const float*)d_in[7];
    const float* bv = (const float*)d_in[8];
    const float* Wo = (const float*)d_in[9];
    const float* bo = (const float*)d_in[10];
    float* out = (float*)d_out;

    int n = in_sizes[0] / D;
    int E = in_sizes[1];
    float qscale = 1.f / sqrtf((float)D);

    static cudaStream_t s2 = nullptr;
    static cudaEvent_t evFork = nullptr, evW = nullptr, evJoin = nullptr;
    if (!s2) {
        cudaStreamCreateWithFlags(&s2, cudaStreamNonBlocking);
        cudaEventCreateWithFlags(&evFork, cudaEventDisableTiming);
        cudaEventCreateWithFlags(&evW, cudaEventDisableTiming);
        cudaEventCreateWithFlags(&evJoin, cudaEventDisableTiming);
    }

    cudaFuncSetAttribute(tgemm_kernel,
                         cudaFuncAttributeMaxDynamicSharedMemorySize, GEMM_SMEM);

    cudaEventRecord(evFork, 0);
    cudaStreamWaitEvent(s2, evFork, 0);

    convw_kernel<<<(4 * D * D / 4 + 255) / 256, 256, 0, s2>>>(Wq, Wk, Wv, Wo);
    cudaEventRecord(evW, s2);
    zero_cnt_kernel<<<(n + 255) / 256, 256, 0, s2>>>(n);
    hist_kernel<<<(E + 255) / 256, 256, 0, s2>>>(dst, E);
    scan_kernel<<<1, 1024, 0, s2>>>(n);
    scatter_kernel<<<(E + 255) / 256, 256, 0, s2>>>(src, dst, E);
    cudaEventRecord(evJoin, s2);

    logmap_kernel<<<n, 128>>>(x, n);
    cudaStreamWaitEvent(0, evW, 0);

    dim3 gqkv(12, (n + 127) / 128);
    tgemm_kernel<<<gqkv, 256, GEMM_SMEM>>>(bq, bk, bv, 0, n, qscale);

    cudaStreamWaitEvent(0, evJoin, 0);
    attn_kernel<<<(n + 7) / 8, 256>>>(n);

    dim3 go(4, (n + 127) / 128);
    tgemm_kernel<<<go, 256, GEMM_SMEM>>>(bo, bo, bo, 1, n, 1.f);
    expmap_kernel<<<n, 128>>>(out, n);
}

// round 17
// speedup vs baseline: 1.7174x; 1.0423x over previous
#include <cuda_runtime.h>
#include <cuda_fp16.h>
#include <math.h>
#include <stdint.h>

#define D 512
#define NMAX 20000
#define EMAX 320000

// ---------------- scratch (device globals: allocation-free) ----------------
__device__ __half g_th[NMAX * D];    // tangent vectors, fp16
__device__ float  g_q[NMAX * D];     // q (fp32) ; later reused as h
__device__ __half g_kh[NMAX * D];    // k (fp16; attention pass 1)
__device__ __half g_vh[NMAX * D];    // v (fp16; attention pass 3)
__device__ __half g_ah[NMAX * D];    // attn output, fp16 (O-GEMM input)
__device__ __half g_Wh[4 * D * D];   // fp16 weight copies (q,k,v,o)
__device__ int    g_cnt[NMAX];
__device__ int    g_off[NMAX + 1];
__device__ int    g_cur[NMAX];
__device__ int    g_srcs[EMAX];      // src node id in CSR order

__device__ __forceinline__ void cp_async16(void* sptr, const void* gptr, bool pred) {
    uint32_t sa = (uint32_t)__cvta_generic_to_shared(sptr);
    int sz = pred ? 16 : 0;
    asm volatile("cp.async.cg.shared.global [%0], [%1], 16, %2;\n"
                 :: "r"(sa), "l"(gptr), "r"(sz));
}

__device__ __forceinline__ uint32_t h2bits(__half2 h) {
    return *reinterpret_cast<uint32_t*>(&h);
}

// ---------------- W conversion (fp16 round, once per call) -----------------
__global__ void convw_kernel(const float* __restrict__ Wq, const float* __restrict__ Wk,
                             const float* __restrict__ Wv, const float* __restrict__ Wo) {
    int i = blockIdx.x * blockDim.x + threadIdx.x;   // float4 index
    int total = 4 * D * D / 4;
    if (i >= total) return;
    int which = i / (D * D / 4);
    int off = i - which * (D * D / 4);
    const float* src = (which == 0) ? Wq : (which == 1) ? Wk : (which == 2) ? Wv : Wo;
    float4 v = ((const float4*)src)[off];
    uint2 o;
    o.x = h2bits(__floats2half2_rn(v.x, v.y));
    o.y = h2bits(__floats2half2_rn(v.z, v.w));
    ((uint2*)(g_Wh + (size_t)which * D * D))[off] = o;
}

// ---------------- logmap0 (writes fp16 tangent) ----------------------------
__global__ void logmap_kernel(const float* __restrict__ x, int n) {
    int row = blockIdx.x;
    if (row >= n) return;
    const float4* xr = (const float4*)(x + (size_t)row * D);
    float4 xv = xr[threadIdx.x];
    float ss = xv.x * xv.x + xv.y * xv.y + xv.z * xv.z + xv.w * xv.w;
    for (int o = 16; o > 0; o >>= 1) ss += __shfl_down_sync(0xffffffffu, ss, o);
    __shared__ float sred[4];
    int lane = threadIdx.x & 31, w = threadIdx.x >> 5;
    if (lane == 0) sred[w] = ss;
    __syncthreads();
    float tot = sred[0] + sred[1] + sred[2] + sred[3];
    float nrm = sqrtf(tot);
    float nc = fminf(fmaxf(nrm, 1e-7f), 1.f - 1e-6f);
    float fac = atanhf(nc) / nc;
    uint2 o;
    o.x = h2bits(__floats2half2_rn(fac * xv.x, fac * xv.y));
    o.y = h2bits(__floats2half2_rn(fac * xv.z, fac * xv.w));
    ((uint2*)(g_th + (size_t)row * D))[threadIdx.x] = o;
}

// ---------------- expmap0 over node range [r0, r1) -------------------------
__global__ void expmap_kernel(float* __restrict__ out, int r0, int r1) {
    int row = r0 + blockIdx.x;
    if (row >= r1) return;
    const float4* hr = (const float4*)(g_q + (size_t)row * D);
    float4 hv = hr[threadIdx.x];
    float ss = hv.x * hv.x + hv.y * hv.y + hv.z * hv.z + hv.w * hv.w;
    for (int o = 16; o > 0; o >>= 1) ss += __shfl_down_sync(0xffffffffu, ss, o);
    __shared__ float sred[4];
    int lane = threadIdx.x & 31, w = threadIdx.x >> 5;
    if (lane == 0) sred[w] = ss;
    __syncthreads();
    float tot = sred[0] + sred[1] + sred[2] + sred[3];
    float nrm = sqrtf(tot);
    float nc = fmaxf(nrm, 1e-7f);
    float fac = tanhf(nc) / nc;
    float4 o4;
    o4.x = fac * hv.x; o4.y = fac * hv.y; o4.z = fac * hv.z; o4.w = fac * hv.w;
    ((float4*)(out + (size_t)row * D))[threadIdx.x] = o4;
}

// ---------------- FP16 tensor-core GEMM (4-stage, m16n8k16, ldmatrix) ------
//   C[rows m0.., 512] = (A @ W^T + bias) * scale ; fp32 accumulate
// mode 0 (QKV): grid.x = 12, sel = bx>>2 (0/1/2), bn = (bx&3)*128, A = g_th
// mode 1 (O):   grid.x = 4,  sel = 3, bn = bx*128, A = g_ah, C = g_q
#define HSTRIDE 40
#define TILE_HALFS (128 * HSTRIDE)
#define NSTAGE 4
#define GEMM_SMEM (NSTAGE * 2 * TILE_HALFS * 2)   // 81920 bytes

__global__ __launch_bounds__(256, 2)
void tgemm_kernel(const float* __restrict__ b0, const float* __restrict__ b1,
                  const float* __restrict__ b2, int mode, int m0, int M,
                  float qscale) {
    extern __shared__ __half smem_h[];
    int sel, bn;
    if (mode == 0) { sel = blockIdx.x >> 2; bn = (blockIdx.x & 3) << 7; }
    else           { sel = 3;               bn = blockIdx.x << 7; }
    const __half* __restrict__ A = (sel == 3) ? g_ah : g_th;
    const __half* __restrict__ W = g_Wh + (size_t)sel * D * D;
    const float* __restrict__ bias = (sel == 1) ? b1 : (sel == 2) ? b2 : b0;
    float scale = (sel == 0) ? qscale : 1.f;

    int bm = m0 + blockIdx.y * 128;
    int tid = threadIdx.x;
    int lane = tid & 31, warp = tid >> 5;
    int wm = (warp >> 2) * 64;
    int wn = (warp & 3) * 32;
    int g = lane >> 2, tg = lane & 3;

    uint32_t smem_base = (uint32_t)__cvta_generic_to_shared(smem_h);

    float acc[4][4][4];
#pragma unroll
    for (int mt = 0; mt < 4; mt++)
#pragma unroll
        for (int nt = 0; nt < 4; nt++)
#pragma unroll
            for (int i = 0; i < 4; i++) acc[mt][nt][i] = 0.f;

    auto prefetch = [&](int it) {
        __half* As = smem_h + (it % NSTAGE) * 2 * TILE_HALFS;
        __half* Ws = As + TILE_HALFS;
        int k0 = it * 32;
#pragma unroll
        for (int i = 0; i < 2; i++) {
            int ci = tid + i * 256;
            int row = ci >> 2, col8 = (ci & 3) * 8;
            int ga = bm + row;
            cp_async16(&As[row * HSTRIDE + col8],
                       A + (size_t)ga * D + k0 + col8, ga < M);
            cp_async16(&Ws[row * HSTRIDE + col8],
                       W + (size_t)(bn + row) * D + k0 + col8, true);
        }
        asm volatile("cp.async.commit_group;\n" ::);
    };

    prefetch(0);
    prefetch(1);
    prefetch(2);

    int a_row_off = (lane & 7) + ((lane >> 3) & 1) * 8;
    int a_k_off = (lane >> 4) * 8;
    int b_row_off = lane & 7;
    int b_k_off = ((lane >> 3) & 1) * 8;

    for (int it = 0; it < 16; it++) {
        if (it < 14) {
            asm volatile("cp.async.wait_group 2;\n" ::);
        } else if (it < 15) {
            asm volatile("cp.async.wait_group 1;\n" ::);
        } else {
            asm volatile("cp.async.wait_group 0;\n" ::);
        }
        __syncthreads();
        if (it + 3 < 16) prefetch(it + 3);

        uint32_t a_base = smem_base + (uint32_t)((it % NSTAGE) * 2 * TILE_HALFS) * 2;
        uint32_t w_base = a_base + (uint32_t)TILE_HALFS * 2;

#pragma unroll
        for (int ks = 0; ks < 2; ks++) {
            int kh = ks * 16;
            uint32_t af[4][4], bf[4][2];
#pragma unroll
            for (int mt = 0; mt < 4; mt++) {
                int r = wm + mt * 16 + a_row_off;
                uint32_t addr = a_base + (uint32_t)(r * HSTRIDE + kh + a_k_off) * 2;
                asm volatile(
                    "ldmatrix.sync.aligned.m8n8.x4.shared.b16 {%0,%1,%2,%3}, [%4];"
                    : "=r"(af[mt][0]), "=r"(af[mt][1]),
                      "=r"(af[mt][2]), "=r"(af[mt][3])
                    : "r"(addr));
            }
#pragma unroll
            for (int nt = 0; nt < 4; nt++) {
                int r = wn + nt * 8 + b_row_off;
                uint32_t addr = w_base + (uint32_t)(r * HSTRIDE + kh + b_k_off) * 2;
                asm volatile(
                    "ldmatrix.sync.aligned.m8n8.x2.shared.b16 {%0,%1}, [%2];"
                    : "=r"(bf[nt][0]), "=r"(bf[nt][1])
                    : "r"(addr));
            }
#pragma unroll
            for (int mt = 0; mt < 4; mt++)
#pragma unroll
                for (int nt = 0; nt < 4; nt++) {
                    asm volatile(
                        "mma.sync.aligned.m16n8k16.row.col.f32.f16.f16.f32 "
                        "{%0,%1,%2,%3}, {%4,%5,%6,%7}, {%8,%9}, {%0,%1,%2,%3};"
                        : "+f"(acc[mt][nt][0]), "+f"(acc[mt][nt][1]),
                          "+f"(acc[mt][nt][2]), "+f"(acc[mt][nt][3])
                        : "r"(af[mt][0]), "r"(af[mt][1]),
                          "r"(af[mt][2]), "r"(af[mt][3]),
                          "r"(bf[nt][0]), "r"(bf[nt][1]));
                }
        }
    }

#pragma unroll
    for (int mt = 0; mt < 4; mt++) {
        int row0 = bm + wm + mt * 16 + g;
#pragma unroll
        for (int nt = 0; nt < 4; nt++) {
            int col = bn + wn + nt * 8 + tg * 2;
            float b0v = bias[col], b1v = bias[col + 1];
            if (sel == 1 || sel == 2) {
                __half* dst16 = (sel == 1) ? g_kh : g_vh;
                if (row0 < M) {
                    __half2 h = __floats2half2_rn(acc[mt][nt][0] + b0v,
                                                  acc[mt][nt][1] + b1v);
                    *(__half2*)(dst16 + (size_t)row0 * D + col) = h;
                }
                if (row0 + 8 < M) {
                    __half2 h = __floats2half2_rn(acc[mt][nt][2] + b0v,
                                                  acc[mt][nt][3] + b1v);
                    *(__half2*)(dst16 + (size_t)(row0 + 8) * D + col) = h;
                }
            } else {
                if (row0 < M) {
                    float2 o;
                    o.x = (acc[mt][nt][0] + b0v) * scale;
                    o.y = (acc[mt][nt][1] + b1v) * scale;
                    *(float2*)(g_q + (size_t)row0 * D + col) = o;
                }
                if (row0 + 8 < M) {
                    float2 o;
                    o.x = (acc[mt][nt][2] + b0v) * scale;
                    o.y = (acc[mt][nt][3] + b1v) * scale;
                    *(float2*)(g_q + (size_t)(row0 + 8) * D + col) = o;
                }
            }
        }
    }
}

// ---------------- CSR build (by dst) ----------------
__global__ void zero_cnt_kernel(int n) {
    int i = blockIdx.x * blockDim.x + threadIdx.x;
    if (i < n) g_cnt[i] = 0;
}
__global__ void hist_kernel(const int* __restrict__ dst, int E) {
    int i = blockIdx.x * blockDim.x + threadIdx.x;
    if (i < E) atomicAdd(&g_cnt[dst[i]], 1);
}
__global__ void scan_kernel(int n) {
    __shared__ int sdata[1024];
    __shared__ int carry_s;
    int t = threadIdx.x;
    if (t == 0) carry_s = 0;
    __syncthreads();
    for (int base = 0; base < n; base += 1024) {
        int idx = base + t;
        int v = (idx < n) ? g_cnt[idx] : 0;
        sdata[t] = v;
        __syncthreads();
        for (int off = 1; off < 1024; off <<= 1) {
            int tmp = (t >= off) ? sdata[t - off] : 0;
            __syncthreads();
            sdata[t] += tmp;
            __syncthreads();
        }
        int incl = sdata[t];
        int carry = carry_s;
        if (idx < n) {
            int excl = carry + incl - v;
            g_off[idx] = excl;
            g_cur[idx] = excl;
        }
        __syncthreads();
        if (t == 1023) carry_s = carry + incl;
        __syncthreads();
    }
    if (t == 0) g_off[n] = carry_s;
}
__global__ void scatter_kernel(const int* __restrict__ src,
                               const int* __restrict__ dst, int E) {
    int i = blockIdx.x * blockDim.x + threadIdx.x;
    if (i < E) {
        int p = atomicAdd(&g_cur[dst[i]], 1);
        g_srcs[p] = src[i];
    }
}

// ---------------- warp-per-dst attention over node range [r0, r1) ----------
__global__ __launch_bounds__(256)
void attn_kernel(int r0, int r1) {
    const unsigned FULL = 0xffffffffu;
    int lane = threadIdx.x & 31;
    int dnode = r0 + blockIdx.x * 8 + (threadIdx.x >> 5);
    if (dnode >= r1) return;
    int beg = g_off[dnode], deg = g_off[dnode + 1] - beg;

    const float4* qr = (const float4*)(g_q + (size_t)dnode * D);
    float4 q4[4];
    q4[0] = qr[lane * 2];
    q4[1] = qr[lane * 2 + 1];
    q4[2] = qr[64 + lane * 2];
    q4[3] = qr[64 + lane * 2 + 1];

    // pass 1: whole-warp dot per edge against fp16 k rows
    float sc[4];
    float wmax = -3.4e38f;
    for (int idx = 0; idx < deg; idx++) {
        int s = g_srcs[beg + idx];
        const uint4* kr = (const uint4*)(g_kh + (size_t)s * D);
        uint4 r0v = kr[lane];
        uint4 r1v = kr[lane + 32];
        const __half2* h0 = (const __half2*)&r0v;
        const __half2* h1 = (const __half2*)&r1v;
        float acc = 0.f;
#pragma unroll
        for (int j = 0; j < 2; j++) {
            float2 f0 = __half22float2(h0[2 * j]);
            float2 f1 = __half22float2(h0[2 * j + 1]);
            const float* qp = (const float*)&q4[j];
            acc += f0.x * qp[0] + f0.y * qp[1] + f1.x * qp[2] + f1.y * qp[3];
        }
#pragma unroll
        for (int j = 0; j < 2; j++) {
            float2 f0 = __half22float2(h1[2 * j]);
            float2 f1 = __half22float2(h1[2 * j + 1]);
            const float* qp = (const float*)&q4[2 + j];
            acc += f0.x * qp[0] + f0.y * qp[1] + f1.x * qp[2] + f1.y * qp[3];
        }
#pragma unroll
        for (int o = 16; o > 0; o >>= 1)
            acc += __shfl_down_sync(FULL, acc, o);
        acc = __shfl_sync(FULL, acc, 0);
        if ((idx & 31) == lane) sc[idx >> 5] = acc;
        wmax = fmaxf(wmax, acc);
    }

    // pass 2: exp + denom
    float ex[4];
    float ds = 0.f;
#pragma unroll
    for (int slot = 0; slot < 4; slot++) {
        int idx = slot * 32 + lane;
        if (idx < deg) { ex[slot] = expf(sc[slot] - wmax); ds += ex[slot]; }
        else ex[slot] = 0.f;
    }
#pragma unroll
    for (int o = 16; o > 0; o >>= 1)
        ds += __shfl_down_sync(FULL, ds, o);
    ds = __shfl_sync(FULL, ds, 0);
    float inv = 1.f / ds;

    // pass 3: accumulate fp16 v rows
    float a[16];
#pragma unroll
    for (int i = 0; i < 16; i++) a[i] = 0.f;
    for (int idx = 0; idx < deg; idx++) {
        float al = __shfl_sync(FULL, ex[idx >> 5], idx & 31) * inv;
        int s = g_srcs[beg + idx];
        const uint4* vr = (const uint4*)(g_vh + (size_t)s * D);
        uint4 r0v = vr[lane];
        uint4 r1v = vr[lane + 32];
        const __half2* h0 = (const __half2*)&r0v;
        const __half2* h1 = (const __half2*)&r1v;
#pragma unroll
        for (int j = 0; j < 4; j++) {
            float2 f0 = __half22float2(h0[j]);
            float2 f1 = __half22float2(h1[j]);
            a[2 * j + 0] += al * f0.x;
            a[2 * j + 1] += al * f0.y;
            a[8 + 2 * j + 0] += al * f1.x;
            a[8 + 2 * j + 1] += al * f1.y;
        }
    }

    // writeback as fp16 (O-GEMM input)
    __half* arow = g_ah + (size_t)dnode * D;
    uint4 u0, u1;
    u0.x = h2bits(__floats2half2_rn(a[0], a[1]));
    u0.y = h2bits(__floats2half2_rn(a[2], a[3]));
    u0.z = h2bits(__floats2half2_rn(a[4], a[5]));
    u0.w = h2bits(__floats2half2_rn(a[6], a[7]));
    u1.x = h2bits(__floats2half2_rn(a[8], a[9]));
    u1.y = h2bits(__floats2half2_rn(a[10], a[11]));
    u1.z = h2bits(__floats2half2_rn(a[12], a[13]));
    u1.w = h2bits(__floats2half2_rn(a[14], a[15]));
    ((uint4*)arow)[lane] = u0;
    ((uint4*)(arow + 256))[lane] = u1;
}

// ---------------- launch ----------------
extern "C" void kernel_launch(void* const* d_in, const int* in_sizes, int n_in,
                              void* d_out, int out_size) {
    const float* x  = (const float*)d_in[0];
    const int*   src = (const int*)d_in[1];
    const int*   dst = (const int*)d_in[2];
    const float* Wq = (const float*)d_in[3];
    const float* bq = (const float*)d_in[4];
    const float* Wk = (const float*)d_in[5];
    const float* bk = (const float*)d_in[6];
    const float* Wv = (const float*)d_in[7];
    const float* bv = (const float*)d_in[8];
    const float* Wo = (const float*)d_in[9];
    const float* bo = (const float*)d_in[10];
    float* out = (float*)d_out;

    int n = in_sizes[0] / D;
    int E = in_sizes[1];
    float qscale = 1.f / sqrtf((float)D);

    // split point for the attn/O/expmap tail (multiple of 128)
    int n1 = ((n / 2) / 128) * 128;
    int n2 = n - n1;

    static cudaStream_t s2 = nullptr;
    static cudaEvent_t evFork = nullptr, evW = nullptr, evJoin = nullptr,
                       evQKV = nullptr, evDone = nullptr;
    if (!s2) {
        cudaStreamCreateWithFlags(&s2, cudaStreamNonBlocking);
        cudaEventCreateWithFlags(&evFork, cudaEventDisableTiming);
        cudaEventCreateWithFlags(&evW, cudaEventDisableTiming);
        cudaEventCreateWithFlags(&evJoin, cudaEventDisableTiming);
        cudaEventCreateWithFlags(&evQKV, cudaEventDisableTiming);
        cudaEventCreateWithFlags(&evDone, cudaEventDisableTiming);
    }

    cudaFuncSetAttribute(tgemm_kernel,
                         cudaFuncAttributeMaxDynamicSharedMemorySize, GEMM_SMEM);

    cudaEventRecord(evFork, 0);
    cudaStreamWaitEvent(s2, evFork, 0);

    // side stream: weight conversion + CSR build
    convw_kernel<<<(4 * D * D / 4 + 255) / 256, 256, 0, s2>>>(Wq, Wk, Wv, Wo);
    cudaEventRecord(evW, s2);
    zero_cnt_kernel<<<(n + 255) / 256, 256, 0, s2>>>(n);
    hist_kernel<<<(E + 255) / 256, 256, 0, s2>>>(dst, E);
    scan_kernel<<<1, 1024, 0, s2>>>(n);
    scatter_kernel<<<(E + 255) / 256, 256, 0, s2>>>(src, dst, E);
    cudaEventRecord(evJoin, s2);

    // main: logmap -> QKV GEMM
    logmap_kernel<<<n, 128>>>(x, n);
    cudaStreamWaitEvent(0, evW, 0);
    dim3 gqkv(12, (n + 127) / 128);
    tgemm_kernel<<<gqkv, 256, GEMM_SMEM>>>(bq, bk, bv, 0, 0, n, qscale);
    cudaEventRecord(evQKV, 0);

    // tail split: half A on main, half B on s2
    cudaStreamWaitEvent(0, evJoin, 0);
    cudaStreamWaitEvent(s2, evQKV, 0);   // s2 already ordered after evJoin

    // half B (rows n1..n) on s2
    attn_kernel<<<(n2 + 7) / 8, 256, 0, s2>>>(n1, n);
    dim3 goB(4, (n2 + 127) / 128);
    tgemm_kernel<<<goB, 256, GEMM_SMEM, s2>>>(bo, bo, bo, 1, n1, n, 1.f);
    expmap_kernel<<<n2, 128, 0, s2>>>(out, n1, n);
    cudaEventRecord(evDone, s2);

    // half A (rows 0..n1) on main
    attn_kernel<<<(n1 + 7) / 8, 256>>>(0, n1);
    dim3 goA(4, n1 / 128);
    tgemm_kernel<<<goA, 256, GEMM_SMEM>>>(bo, bo, bo, 1, 0, n1, 1.f);
    expmap_kernel<<<n1, 128>>>(out, 0, n1);

    cudaStreamWaitEvent(0, evDone, 0);   // join graph sink on main
}